// round 6
// baseline (speedup 1.0000x reference)
#include <cuda_runtime.h>
#include <cuda_fp16.h>
#include <cstdint>
#include <cstddef>

// Problem constants
#define Bb 32
#define Ll 2048
#define Uu 512
#define Hh 8
#define HDd 64
#define NPOS (Bb * Ll)      // 65536
#define MCH 1536            // q|k|v channels (cmax indexing)
#define KVW 1024            // stored channels (k,v only), fp16
#define LGS 2049            // logits per (b,h)
#define NSL 8               // attention slices

// GEMM config: M = positions, N = channels, K = 3*512
#define TM 128
#define TN 128
#define BK 64
#define NCHUNK 24           // 1536 / 64
#define STAGE 32768         // 16KB A + 16KB B
#define NSTAGE 3

// ---------------------------------------------------------------------------
// Device scratch
// ---------------------------------------------------------------------------
__device__ __align__(16) __half g_Th[(size_t)NPOS * Uu];      // fp16(t), 64MB
__device__ __align__(16) __half g_Wh[(size_t)MCH * MCH];      // fp16 W [m][tau*512+k]
__device__ __align__(16) __half g_Yh[(size_t)NPOS * KVW];     // k|v conv out fp16, 128MB
__device__ float g_bias[MCH];
__device__ float g_cmax[Bb * MCH];
__device__ float g_lg[Bb * Hh * LGS];                         // logits -> probs
__device__ float g_part[Bb * Hh * NSL * HDd];                 // V partial sums

// ---------------------------------------------------------------------------
// Helpers
// ---------------------------------------------------------------------------
__device__ __forceinline__ void cp16(uint32_t dst, const void* src, bool valid) {
    int sz = valid ? 16 : 0;
    asm volatile("cp.async.cg.shared.global [%0], [%1], 16, %2;\n"
                 :: "r"(dst), "l"(src), "r"(sz));
}
#define CP_COMMIT() asm volatile("cp.async.commit_group;" ::: "memory")
#define CP_WAIT(n)  asm volatile("cp.async.wait_group %0;" :: "n"(n) : "memory")

__device__ __forceinline__ uint32_t su32(const void* p) {
    uint32_t a;
    asm("{ .reg .u64 t; cvta.to.shared.u64 t, %1; cvt.u32.u64 %0, t; }" : "=r"(a) : "l"(p));
    return a;
}

// fp16-accumulate MMA: D,C are 2 regs of f16x2
__device__ __forceinline__ void mma_f16acc(uint32_t c[2],
                                           uint32_t a0, uint32_t a1, uint32_t a2, uint32_t a3,
                                           uint32_t b0, uint32_t b1) {
    asm volatile(
        "mma.sync.aligned.m16n8k16.row.col.f16.f16.f16.f16 "
        "{%0,%1}, {%2,%3,%4,%5}, {%6,%7}, {%0,%1};\n"
        : "+r"(c[0]), "+r"(c[1])
        : "r"(a0), "r"(a1), "r"(a2), "r"(a3), "r"(b0), "r"(b1));
}

__device__ __forceinline__ void atomicMaxF(float* a, float v) {
    if (v >= 0.f) atomicMax((int*)a, __float_as_int(v));
    else          atomicMin((unsigned*)a, __float_as_uint(v));
}

// fragment LDS from a swizzled tile: row stride 128B, 16B-chunk XOR (row&7)
__device__ __forceinline__ uint32_t lds_frag(const char* base, int row, int h) {
    int chunk = h >> 3;
    int off   = (h & 7) * 2;
    return *(const uint32_t*)(base + row * 128 + ((chunk ^ (row & 7)) << 4) + off);
}

// ---------------------------------------------------------------------------
// t -> fp16
// ---------------------------------------------------------------------------
__global__ void tconv_kernel(const float* __restrict__ t) {
    size_t gid = (size_t)blockIdx.x * blockDim.x + threadIdx.x;   // float4 index
    if (gid >= (size_t)NPOS * Uu / 4) return;
    float4 v = ((const float4*)t)[gid];
    __half2 h0 = __floats2half2_rn(v.x, v.y);
    __half2 h1 = __floats2half2_rn(v.z, v.w);
    ((uint2*)g_Th)[gid] = make_uint2(*(uint32_t*)&h0, *(uint32_t*)&h1);
}

// ---------------------------------------------------------------------------
// weights -> fp16 [m][tau*512+k] (K-major rows), bias
// ---------------------------------------------------------------------------
__global__ void repack_kernel(const float* __restrict__ Wq, const float* __restrict__ bq,
                              const float* __restrict__ Wk, const float* __restrict__ bk,
                              const float* __restrict__ Wv, const float* __restrict__ bv) {
    int gid = blockIdx.x * blockDim.x + threadIdx.x;
    if (gid < MCH)
        g_bias[gid] = gid < 512 ? bq[gid] : (gid < 1024 ? bk[gid - 512] : bv[gid - 1024]);
    if (gid >= MCH * MCH) return;
    int mg   = gid / MCH;
    int kk   = gid % MCH;
    int tau  = kk / 512;
    int k    = kk % 512;
    int conv = mg / 512;
    int m    = mg % 512;
    const float* W = (conv == 0) ? Wq : ((conv == 1) ? Wk : Wv);
    g_Wh[gid] = __float2half_rn(W[m * 1536 + k * 3 + tau]);
}

__global__ void cmax_init_kernel() {
    int gid = blockIdx.x * blockDim.x + threadIdx.x;
    if (gid < Bb * MCH) ((unsigned*)g_cmax)[gid] = 0xff800000u;   // -inf
}

// ---------------------------------------------------------------------------
// fused qkv conv: fp16 HMMA GEMM (fp16 intra-chunk accumulate, fp32 promote
// per BK=64 chunk), 128x128 tile, 3-stage cp.async pipeline.
// Epilogue: +bias, channel max, fp16 k/v store.
// ---------------------------------------------------------------------------
__global__ __launch_bounds__(256, 1) void conv_hmma_kernel() {
    extern __shared__ __align__(128) char dsmem[];   // 3 * 32KB
    __shared__ float bias_s[TN];

    const int tid  = threadIdx.x;
    const int wid  = tid >> 5;
    const int lane = tid & 31;
    const int g    = lane >> 2;
    const int tg   = lane & 3;
    const int wm   = wid >> 1;          // 0..3: M strip of 32
    const int wn   = wid & 1;           // 0..1: N strip of 64
    const int m0   = blockIdx.x * TN;
    const int n0   = blockIdx.y * TM;
    const int b    = n0 >> 11;
    const int l0   = n0 & 2047;

    if (tid < TN) bias_s[tid] = g_bias[m0 + tid];

    const uint32_t smem0 = su32(dsmem);

    auto load_chunk = [&](int c, int slot) {
        const int tau = c >> 3;
        const int k0  = (c & 7) * BK;
        const uint32_t abase = smem0 + (uint32_t)slot * STAGE;
        const uint32_t bbase = abase + 16384u;
#pragma unroll
        for (int p = 0; p < 4; p++) {
            int idx = p * 256 + tid;       // 0..1023
            int row = idx >> 3;
            int j   = idx & 7;
            int l   = l0 + row + tau - 1;
            bool ok = (l >= 0 && l < Ll);
            const void* src = g_Th + ((size_t)(b * Ll + (ok ? l : 0))) * Uu + k0 + j * 8;
            cp16(abase + (uint32_t)(row * 128 + ((j ^ (row & 7)) << 4)), src, ok);
        }
#pragma unroll
        for (int p = 0; p < 4; p++) {
            int idx = p * 256 + tid;
            int row = idx >> 3;
            int j   = idx & 7;
            const void* src = g_Wh + (size_t)(m0 + row) * MCH + tau * 512 + k0 + j * 8;
            cp16(bbase + (uint32_t)(row * 128 + ((j ^ (row & 7)) << 4)), src, true);
        }
    };

    float acc[2][8][4];
#pragma unroll
    for (int i = 0; i < 2; i++)
#pragma unroll
        for (int j = 0; j < 8; j++)
#pragma unroll
            for (int e = 0; e < 4; e++) acc[i][j][e] = 0.f;

    load_chunk(0, 0); CP_COMMIT();
    load_chunk(1, 1); CP_COMMIT();

    for (int i = 0; i < NCHUNK; i++) {
        if (i + 1 < NCHUNK) { CP_WAIT(1); } else { CP_WAIT(0); }
        __syncthreads();
        if (i + 2 < NCHUNK) { load_chunk(i + 2, (i + 2) % NSTAGE); CP_COMMIT(); }

        const char* Ab   = dsmem + (i % NSTAGE) * STAGE;
        const char* Bbse = Ab + 16384;

        // fp16 accumulators for this chunk
        uint32_t hacc[2][8][2];
#pragma unroll
        for (int mf = 0; mf < 2; mf++)
#pragma unroll
            for (int nf = 0; nf < 8; nf++) { hacc[mf][nf][0] = 0u; hacc[mf][nf][1] = 0u; }

#pragma unroll
        for (int kk = 0; kk < 4; kk++) {
            const int kb = kk * 16;
            uint32_t a[2][4];
#pragma unroll
            for (int mf = 0; mf < 2; mf++) {
                int r0 = wm * 32 + mf * 16 + g;
                a[mf][0] = lds_frag(Ab, r0,     kb + 2 * tg);
                a[mf][1] = lds_frag(Ab, r0 + 8, kb + 2 * tg);
                a[mf][2] = lds_frag(Ab, r0,     kb + 8 + 2 * tg);
                a[mf][3] = lds_frag(Ab, r0 + 8, kb + 8 + 2 * tg);
            }
            uint32_t bf[8][2];
#pragma unroll
            for (int nf = 0; nf < 8; nf++) {
                int rn = wn * 64 + nf * 8 + g;
                bf[nf][0] = lds_frag(Bbse, rn, kb + 2 * tg);
                bf[nf][1] = lds_frag(Bbse, rn, kb + 8 + 2 * tg);
            }
#pragma unroll
            for (int mf = 0; mf < 2; mf++)
#pragma unroll
                for (int nf = 0; nf < 8; nf++)
                    mma_f16acc(hacc[mf][nf], a[mf][0], a[mf][1], a[mf][2], a[mf][3],
                               bf[nf][0], bf[nf][1]);
        }

        // promote chunk result to fp32
#pragma unroll
        for (int mf = 0; mf < 2; mf++)
#pragma unroll
            for (int nf = 0; nf < 8; nf++) {
                float2 lo = __half22float2(*(__half2*)&hacc[mf][nf][0]);
                float2 hi = __half22float2(*(__half2*)&hacc[mf][nf][1]);
                acc[mf][nf][0] += lo.x;
                acc[mf][nf][1] += lo.y;
                acc[mf][nf][2] += hi.x;
                acc[mf][nf][3] += hi.y;
            }
    }

    // ---- epilogue: bias, channel max, fp16 k/v store ----
    const bool do_store = (m0 >= 512);
#pragma unroll
    for (int nf = 0; nf < 8; nf++) {
        const int col = m0 + wn * 64 + nf * 8 + 2 * tg;
        const float b0 = bias_s[col - m0], b1 = bias_s[col - m0 + 1];
        float cm0 = -3.4e38f, cm1 = -3.4e38f;
#pragma unroll
        for (int mf = 0; mf < 2; mf++) {
            float v0 = acc[mf][nf][0] + b0;
            float v1 = acc[mf][nf][1] + b1;
            float v2 = acc[mf][nf][2] + b0;
            float v3 = acc[mf][nf][3] + b1;
            if (do_store) {
                size_t n = (size_t)n0 + wm * 32 + mf * 16 + g;
                __half2* p = (__half2*)(g_Yh + n * KVW + (col - 512));
                *p = __floats2half2_rn(v0, v1);
                *(__half2*)((char*)p + (size_t)8 * KVW * 2) = __floats2half2_rn(v2, v3);
            }
            cm0 = fmaxf(cm0, fmaxf(v0, v2));
            cm1 = fmaxf(cm1, fmaxf(v1, v3));
        }
#pragma unroll
        for (int o = 4; o <= 16; o <<= 1) {
            cm0 = fmaxf(cm0, __shfl_xor_sync(0xffffffffu, cm0, o));
            cm1 = fmaxf(cm1, __shfl_xor_sync(0xffffffffu, cm1, o));
        }
        if (lane < 4) {
            atomicMaxF(&g_cmax[b * MCH + col], cm0);
            atomicMaxF(&g_cmax[b * MCH + col + 1], cm1);
        }
    }
}

// ---------------------------------------------------------------------------
// attention stage 1: raw masked logits. grid = 32*8*8 (b, h, slice).
// ---------------------------------------------------------------------------
__global__ __launch_bounds__(256) void logits_kernel(const int* __restrict__ gmask,
                                                     const int* __restrict__ tmask) {
    __shared__ float q_s[64];
    const int bid   = blockIdx.x;
    const int slice = bid & 7;
    const int h     = (bid >> 3) & 7;
    const int b     = bid >> 6;
    const int tid   = threadIdx.x;
    const int lane  = tid & 31;
    const int w     = tid >> 5;

    if (tid < 64) q_s[tid] = g_cmax[b * MCH + h * HDd + tid];
    __syncthreads();

    const float scale = 0.04419417382415922f;   // 1/sqrt(512)
    const int j0  = slice * 256;
    const int cnt = (slice == NSL - 1) ? 257 : 256;
    const __half* Yk = g_Yh + (size_t)b * Ll * KVW + h * HDd;
    float* lg = g_lg + (b * Hh + h) * LGS;

    for (int jj = w; jj < cnt; jj += 8) {
        const int j = j0 + jj;
        float k0f, k1f;
        if (j == 0) {
            k0f = g_cmax[b * MCH + 512 + h * HDd + 2 * lane];
            k1f = g_cmax[b * MCH + 512 + h * HDd + 2 * lane + 1];
        } else {
            int l = j - 1;
            const __half2* r = (const __half2*)(Yk + (size_t)l * KVW) + lane;
            __half2 kv = r[0];
            if (l > 0)      kv = __hmax2(kv, r[-(KVW / 2)]);
            if (l < Ll - 1) kv = __hmax2(kv, r[KVW / 2]);
            float2 kf = __half22float2(kv);
            k0f = kf.x; k1f = kf.y;
        }
        float p = q_s[2 * lane] * k0f + q_s[2 * lane + 1] * k1f;
#pragma unroll
        for (int o = 16; o; o >>= 1) p += __shfl_down_sync(0xffffffffu, p, o);
        if (lane == 0) {
            int mk = (j == 0) ? gmask[b] : tmask[b * Ll + (j - 1)];
            lg[j] = mk ? p * scale : -1e30f;
        }
    }
}

// ---------------------------------------------------------------------------
// attention stage 2: softmax in place, probs scaled by 1/sum and g_mask.
// ---------------------------------------------------------------------------
__global__ __launch_bounds__(256) void softmax_kernel(const int* __restrict__ gmask) {
    __shared__ float red[256];
    const int b   = blockIdx.x >> 3;
    const int h   = blockIdx.x & 7;
    const int tid = threadIdx.x;
    float* lg = g_lg + (b * Hh + h) * LGS;

    float lm = -1e30f;
    for (int j = tid; j < LGS; j += 256) lm = fmaxf(lm, lg[j]);
    red[tid] = lm;
    __syncthreads();
    for (int s = 128; s; s >>= 1) {
        if (tid < s) red[tid] = fmaxf(red[tid], red[tid + s]);
        __syncthreads();
    }
    const float mx = red[0];
    __syncthreads();

    float ls = 0.f;
    float ev[9];
    int nv = 0;
    for (int j = tid; j < LGS; j += 256) {
        float e = expf(lg[j] - mx);
        ev[nv++] = e;
        ls += e;
    }
    red[tid] = ls;
    __syncthreads();
    for (int s = 128; s; s >>= 1) {
        if (tid < s) red[tid] += red[tid + s];
        __syncthreads();
    }
    const float fac = (1.0f / red[0]) * (float)gmask[b];
    nv = 0;
    for (int j = tid; j < LGS; j += 256) lg[j] = ev[nv++] * fac;
}

// ---------------------------------------------------------------------------
// attention stage 3: weighted V sum partials. grid = 32*8*8 (b, h, slice)
// ---------------------------------------------------------------------------
__global__ __launch_bounds__(256) void vsum_kernel() {
    __shared__ float red[256];
    const int bid   = blockIdx.x;
    const int slice = bid & 7;
    const int h     = (bid >> 3) & 7;
    const int b     = bid >> 6;
    const int tid   = threadIdx.x;
    const int d     = tid & 63;
    const int grp   = tid >> 6;

    const int j0  = slice * 256;
    const int cnt = (slice == NSL - 1) ? 257 : 256;
    const __half* Yv = g_Yh + (size_t)b * Ll * KVW + 512 + h * HDd + d;
    const float* lg = g_lg + (b * Hh + h) * LGS;

    float acc = 0.f;
    for (int jj = grp; jj < cnt; jj += 4) {
        const int j = j0 + jj;
        float v;
        if (j == 0) {
            v = g_cmax[b * MCH + 1024 + h * HDd + d];
        } else {
            int l = j - 1;
            const __half* r = Yv + (size_t)l * KVW;
            __half hv = r[0];
            if (l > 0)      hv = __hmax(hv, r[-KVW]);
            if (l < Ll - 1) hv = __hmax(hv, r[KVW]);
            v = __half2float(hv);
        }
        acc += lg[j] * v;
    }
    red[tid] = acc;
    __syncthreads();
    if (tid < 64) {
        float o = red[tid] + red[tid + 64] + red[tid + 128] + red[tid + 192];
        g_part[((b * Hh + h) * NSL + slice) * HDd + d] = o;
    }
}

// ---------------------------------------------------------------------------
// final: reduce slice partials, head-mix (Wh 8x8), output 1x1 conv (Wo).
// grid = (32 batches, 4 output quarters), 512 threads.
// ---------------------------------------------------------------------------
__global__ __launch_bounds__(512) void final_kernel(const float* __restrict__ Wh,
                                                    const float* __restrict__ bh,
                                                    const float* __restrict__ Wo,
                                                    const float* __restrict__ bo,
                                                    float* __restrict__ out) {
    const int b    = blockIdx.x;
    const int quad = blockIdx.y;
    const int tid  = threadIdx.x;
    __shared__ float att_s[512];   // (h, d)
    __shared__ float mid[512];

    {
        const int h = tid >> 6, d = tid & 63;
        const float* p = g_part + ((b * Hh + h) * NSL) * HDd + d;
        float s = 0.f;
#pragma unroll
        for (int sl = 0; sl < NSL; sl++) s += p[sl * HDd];
        att_s[tid] = s;
    }
    __syncthreads();

    {
        const int oh = tid >> 6, d = tid & 63;
        float s = bh[oh];
#pragma unroll
        for (int i = 0; i < 8; i++) s += Wh[oh * 8 + i] * att_s[i * HDd + d];
        mid[tid] = s;
    }
    __syncthreads();

    const int o    = quad * 128 + (tid >> 2);
    const int part = tid & 3;
    const float* wr = Wo + (size_t)o * 512 + part * 128;
    const float* mr = mid + part * 128;
    float s = 0.f;
#pragma unroll 16
    for (int i = 0; i < 128; i++) s += wr[i] * mr[i];
    s += __shfl_xor_sync(0xffffffffu, s, 1);
    s += __shfl_xor_sync(0xffffffffu, s, 2);
    if (part == 0) out[b * 512 + o] = s + bo[o];
}

// ---------------------------------------------------------------------------
// Launch
// ---------------------------------------------------------------------------
extern "C" void kernel_launch(void* const* d_in, const int* in_sizes, int n_in,
                              void* d_out, int out_size) {
    const float* t     = (const float*)d_in[0];
    const int*   gmask = (const int*)d_in[2];
    const int*   tmask = (const int*)d_in[3];
    const float* Wq    = (const float*)d_in[4];
    const float* bq    = (const float*)d_in[5];
    const float* Wk    = (const float*)d_in[6];
    const float* bk    = (const float*)d_in[7];
    const float* Wv    = (const float*)d_in[8];
    const float* bv    = (const float*)d_in[9];
    const float* Wh    = (const float*)d_in[10];
    const float* bh    = (const float*)d_in[11];
    const float* Wo    = (const float*)d_in[12];
    const float* bo    = (const float*)d_in[13];
    float* out = (float*)d_out;

    cudaFuncSetAttribute(conv_hmma_kernel, cudaFuncAttributeMaxDynamicSharedMemorySize,
                         NSTAGE * STAGE);

    tconv_kernel<<<(int)(((size_t)NPOS * Uu / 4 + 255) / 256), 256>>>(t);
    repack_kernel<<<(MCH * MCH + 255) / 256, 256>>>(Wq, bq, Wk, bk, Wv, bv);
    cmax_init_kernel<<<(Bb * MCH + 255) / 256, 256>>>();
    conv_hmma_kernel<<<dim3(MCH / TN, NPOS / TM), 256, NSTAGE * STAGE>>>();
    logits_kernel<<<Bb * Hh * NSL, 256>>>(gmask, tmask);
    softmax_kernel<<<Bb * Hh, 256>>>(gmask);
    vsum_kernel<<<Bb * Hh * NSL, 256>>>();
    final_kernel<<<dim3(Bb, 4), 512>>>(Wh, bh, Wo, bo, out);
}

// round 7
// speedup vs baseline: 1.2143x; 1.2143x over previous
#include <cuda_runtime.h>
#include <cuda_fp16.h>
#include <cstdint>
#include <cstddef>

// Problem constants
#define Bb 32
#define Ll 2048
#define Uu 512
#define Hh 8
#define HDd 64
#define NPOS (Bb * Ll)      // 65536
#define MCH 1536            // q|k|v channels (cmax indexing)
#define KVW 1024            // stored channels (k,v only), fp16
#define LGS 2049            // logits per (b,h)
#define NSL 8               // attention slices
#define NPAIR 32768         // Winograd output pairs (NPOS/2)

// Winograd GEMM config: M = pairs, N = channels, K = 512 per g, 4 g's
#define PB 64               // pairs per block tile
#define TNW 128             // channels per block tile
#define BKW 64
#define NCHUNKW 32          // 4 g * (512/64)
#define A_BYTES_W 8192      // 64 pairs * 64 k * 2B
#define B_BYTES_W 16384     // 128 ch * 64 k * 2B
#define STAGEW 24576
#define NSTAGEW 3

// ---------------------------------------------------------------------------
// Device scratch
// ---------------------------------------------------------------------------
__device__ __align__(16) __half g_V[4ull * NPAIR * 512];      // Winograd inputs, 128MB
__device__ __align__(16) __half g_U[4ull * MCH * 512];        // Winograd weights, 6MB
__device__ __align__(16) __half g_Yh[(size_t)NPOS * KVW];     // k|v conv out fp16, 128MB
__device__ float g_bias[MCH];
__device__ float g_cmax[Bb * MCH];
__device__ float g_lg[Bb * Hh * LGS];                         // logits -> probs
__device__ float g_part[Bb * Hh * NSL * HDd];                 // V partial sums

// ---------------------------------------------------------------------------
// Helpers
// ---------------------------------------------------------------------------
__device__ __forceinline__ void cp16(uint32_t dst, const void* src) {
    asm volatile("cp.async.cg.shared.global [%0], [%1], 16;\n"
                 :: "r"(dst), "l"(src));
}
#define CP_COMMIT() asm volatile("cp.async.commit_group;" ::: "memory")
#define CP_WAIT(n)  asm volatile("cp.async.wait_group %0;" :: "n"(n) : "memory")

__device__ __forceinline__ uint32_t su32(const void* p) {
    uint32_t a;
    asm("{ .reg .u64 t; cvta.to.shared.u64 t, %1; cvt.u32.u64 %0, t; }" : "=r"(a) : "l"(p));
    return a;
}

__device__ __forceinline__ void mma_f16(float c[4],
                                        uint32_t a0, uint32_t a1, uint32_t a2, uint32_t a3,
                                        uint32_t b0, uint32_t b1) {
    asm volatile(
        "mma.sync.aligned.m16n8k16.row.col.f32.f16.f16.f32 "
        "{%0,%1,%2,%3}, {%4,%5,%6,%7}, {%8,%9}, {%0,%1,%2,%3};\n"
        : "+f"(c[0]), "+f"(c[1]), "+f"(c[2]), "+f"(c[3])
        : "r"(a0), "r"(a1), "r"(a2), "r"(a3), "r"(b0), "r"(b1));
}

__device__ __forceinline__ void atomicMaxF(float* a, float v) {
    if (v >= 0.f) atomicMax((int*)a, __float_as_int(v));
    else          atomicMin((unsigned*)a, __float_as_uint(v));
}

// fragment LDS from a swizzled tile: row stride 128B, 16B-chunk XOR (row&7)
__device__ __forceinline__ uint32_t lds_frag(const char* base, int row, int h) {
    int chunk = h >> 3;
    int off   = (h & 7) * 2;
    return *(const uint32_t*)(base + row * 128 + ((chunk ^ (row & 7)) << 4) + off);
}

// ---------------------------------------------------------------------------
// Winograd input transform: t(float) -> 4 fp16 arrays V_g[pair][512]
// pair p: window w0..w3 = x[2p-1 .. 2p+2] (zero at batch edges)
// d0=w0-w2, d1=w1+w2, d2=w2-w1, d3=w1-w3
// ---------------------------------------------------------------------------
__global__ __launch_bounds__(256) void vtrans_kernel(const float* __restrict__ t) {
    int gid = blockIdx.x * 256 + threadIdx.x;        // NPAIR * 128
    if (gid >= NPAIR * 128) return;
    const int pair = gid >> 7;
    const int cg   = (gid & 127) << 2;
    const int lp   = pair & 1023;
    const float* base = t + ((size_t)pair * 2) * Uu + cg;   // x[2p] row (global)

    float4 w1 = *(const float4*)(base);
    float4 w2 = *(const float4*)(base + Uu);
    float4 w0 = make_float4(0.f, 0.f, 0.f, 0.f);
    float4 w3 = make_float4(0.f, 0.f, 0.f, 0.f);
    if (lp > 0)    w0 = *(const float4*)(base - Uu);
    if (lp < 1023) w3 = *(const float4*)(base + 2 * Uu);

    const size_t eo = (size_t)pair * 512 + cg;       // element offset within one V_g
    auto st = [&](int g, float a, float b, float c, float d) {
        __half2 lo = __floats2half2_rn(a, b);
        __half2 hi = __floats2half2_rn(c, d);
        *(uint2*)(g_V + (size_t)g * NPAIR * 512 + eo) =
            make_uint2(*(uint32_t*)&lo, *(uint32_t*)&hi);
    };
    st(0, w0.x - w2.x, w0.y - w2.y, w0.z - w2.z, w0.w - w2.w);
    st(1, w1.x + w2.x, w1.y + w2.y, w1.z + w2.z, w1.w + w2.w);
    st(2, w2.x - w1.x, w2.y - w1.y, w2.z - w1.z, w2.w - w1.w);
    st(3, w1.x - w3.x, w1.y - w3.y, w1.z - w3.z, w1.w - w3.w);
}

// ---------------------------------------------------------------------------
// Winograd weight transform: W(q|k|v) -> U_g[m][k] fp16; bias
// u0=g0, u1=(g0+g1+g2)/2, u2=(g0-g1+g2)/2, u3=g2
// ---------------------------------------------------------------------------
__global__ __launch_bounds__(256) void wtrans_kernel(
        const float* __restrict__ Wq, const float* __restrict__ bq,
        const float* __restrict__ Wk, const float* __restrict__ bk,
        const float* __restrict__ Wv, const float* __restrict__ bv) {
    int gid = blockIdx.x * 256 + threadIdx.x;
    if (gid < MCH)
        g_bias[gid] = gid < 512 ? bq[gid] : (gid < 1024 ? bk[gid - 512] : bv[gid - 1024]);
    if (gid >= MCH * 512) return;
    const int mg = gid / 512;
    const int k  = gid % 512;
    const int conv = mg / 512;
    const int m    = mg % 512;
    const float* W = (conv == 0) ? Wq : ((conv == 1) ? Wk : Wv);
    const float g0 = W[m * 1536 + k * 3 + 0];
    const float g1 = W[m * 1536 + k * 3 + 1];
    const float g2 = W[m * 1536 + k * 3 + 2];
    const size_t eo = (size_t)mg * 512 + k;
    g_U[0ull * MCH * 512 + eo] = __float2half_rn(g0);
    g_U[1ull * MCH * 512 + eo] = __float2half_rn(0.5f * (g0 + g1 + g2));
    g_U[2ull * MCH * 512 + eo] = __float2half_rn(0.5f * (g0 - g1 + g2));
    g_U[3ull * MCH * 512 + eo] = __float2half_rn(g2);
}

__global__ void cmax_init_kernel() {
    int gid = blockIdx.x * blockDim.x + threadIdx.x;
    if (gid < Bb * MCH) ((unsigned*)g_cmax)[gid] = 0xff800000u;   // -inf
}

// ---------------------------------------------------------------------------
// Winograd conv GEMM: 64 pairs x 128 channels per block, K=512 per g, 4 g's.
// m_g accumulated per g, folded into y0/y1 with A^T coefficients.
// Epilogue: +bias, channel max, fp16 k/v store (two L-rows per pair).
// ---------------------------------------------------------------------------
__global__ __launch_bounds__(256, 1) void conv_wino_kernel() {
    extern __shared__ __align__(128) char dsmem[];   // 3 * 24KB
    __shared__ float bias_s[TNW];

    const int tid  = threadIdx.x;
    const int wid  = tid >> 5;
    const int lane = tid & 31;
    const int gr   = lane >> 2;
    const int tg   = lane & 3;
    const int wp   = wid & 1;           // 2 warps over pairs (32 each)
    const int wc   = wid >> 1;          // 4 warps over channels (32 each)
    const int m0    = blockIdx.x * TNW;
    const int pair0 = blockIdx.y * PB;
    const int b     = pair0 >> 10;

    if (tid < TNW) bias_s[tid] = g_bias[m0 + tid];

    const uint32_t smem0 = su32(dsmem);

    auto load_chunk = [&](int c, int slot) {
        const int g  = c >> 3;
        const int k0 = (c & 7) * BKW;
        const uint32_t abase = smem0 + (uint32_t)slot * STAGEW;
        const uint32_t bbase = abase + A_BYTES_W;
#pragma unroll
        for (int p = 0; p < 2; p++) {           // A: 64 rows x 8 chunks
            int idx = p * 256 + tid;
            int row = idx >> 3;
            int j   = idx & 7;
            const void* src = g_V + (size_t)g * NPAIR * 512
                              + (size_t)(pair0 + row) * 512 + k0 + j * 8;
            cp16(abase + (uint32_t)(row * 128 + ((j ^ (row & 7)) << 4)), src);
        }
#pragma unroll
        for (int p = 0; p < 4; p++) {           // B: 128 rows x 8 chunks
            int idx = p * 256 + tid;
            int row = idx >> 3;
            int j   = idx & 7;
            const void* src = g_U + (size_t)g * MCH * 512
                              + (size_t)(m0 + row) * 512 + k0 + j * 8;
            cp16(bbase + (uint32_t)(row * 128 + ((j ^ (row & 7)) << 4)), src);
        }
    };

    float y0[2][4][4], y1[2][4][4], macc[2][4][4];
#pragma unroll
    for (int i = 0; i < 2; i++)
#pragma unroll
        for (int j = 0; j < 4; j++)
#pragma unroll
            for (int e = 0; e < 4; e++) { y0[i][j][e] = 0.f; y1[i][j][e] = 0.f; macc[i][j][e] = 0.f; }

    load_chunk(0, 0); CP_COMMIT();
    load_chunk(1, 1); CP_COMMIT();

    for (int c = 0; c < NCHUNKW; c++) {
        if (c + 1 < NCHUNKW) { CP_WAIT(1); } else { CP_WAIT(0); }
        __syncthreads();
        if (c + 2 < NCHUNKW) { load_chunk(c + 2, (c + 2) % NSTAGEW); CP_COMMIT(); }

        const char* Ab = dsmem + (c % NSTAGEW) * STAGEW;
        const char* Bbse = Ab + A_BYTES_W;
#pragma unroll
        for (int kk = 0; kk < 4; kk++) {
            const int kb = kk * 16;
            uint32_t a[2][4];
#pragma unroll
            for (int mt = 0; mt < 2; mt++) {
                int r0 = wp * 32 + mt * 16 + gr;
                a[mt][0] = lds_frag(Ab, r0,     kb + 2 * tg);
                a[mt][1] = lds_frag(Ab, r0 + 8, kb + 2 * tg);
                a[mt][2] = lds_frag(Ab, r0,     kb + 8 + 2 * tg);
                a[mt][3] = lds_frag(Ab, r0 + 8, kb + 8 + 2 * tg);
            }
            uint32_t bf[4][2];
#pragma unroll
            for (int nt = 0; nt < 4; nt++) {
                int rn = wc * 32 + nt * 8 + gr;
                bf[nt][0] = lds_frag(Bbse, rn, kb + 2 * tg);
                bf[nt][1] = lds_frag(Bbse, rn, kb + 8 + 2 * tg);
            }
#pragma unroll
            for (int mt = 0; mt < 2; mt++)
#pragma unroll
                for (int nt = 0; nt < 4; nt++)
                    mma_f16(macc[mt][nt], a[mt][0], a[mt][1], a[mt][2], a[mt][3],
                            bf[nt][0], bf[nt][1]);
        }

        if ((c & 7) == 7) {             // end of g: fold m into y with A^T coeffs
            const int g = c >> 3;
            const float c0 = (g < 3) ? 1.f : 0.f;                       // y0: m0+m1+m2
            const float c1 = (g == 1) ? 1.f : ((g >= 2) ? -1.f : 0.f);  // y1: m1-m2-m3
#pragma unroll
            for (int mt = 0; mt < 2; mt++)
#pragma unroll
                for (int nt = 0; nt < 4; nt++)
#pragma unroll
                    for (int e = 0; e < 4; e++) {
                        y0[mt][nt][e] += c0 * macc[mt][nt][e];
                        y1[mt][nt][e] += c1 * macc[mt][nt][e];
                        macc[mt][nt][e] = 0.f;
                    }
        }
    }

    // ---- epilogue: bias, channel max, fp16 k/v store ----
    const bool do_store = (m0 >= 512);
#pragma unroll
    for (int nt = 0; nt < 4; nt++) {
        const int ch = m0 + wc * 32 + nt * 8 + 2 * tg;
        const float b0 = bias_s[ch - m0], b1 = bias_s[ch - m0 + 1];
        float cm0 = -3.4e38f, cm1 = -3.4e38f;
#pragma unroll
        for (int mt = 0; mt < 2; mt++) {
            const int P = pair0 + wp * 32 + mt * 16 + gr;
            // rows 2P, 2P+1 (c0/c1), and 2(P+8), 2(P+8)+1 (c2/c3)
            float v00 = y0[mt][nt][0] + b0, v01 = y0[mt][nt][1] + b1;   // Y[2P]
            float w00 = y1[mt][nt][0] + b0, w01 = y1[mt][nt][1] + b1;   // Y[2P+1]
            float v10 = y0[mt][nt][2] + b0, v11 = y0[mt][nt][3] + b1;   // Y[2P+16]
            float w10 = y1[mt][nt][2] + b0, w11 = y1[mt][nt][3] + b1;   // Y[2P+17]
            if (do_store) {
                __half* base = g_Yh + (size_t)(2 * P) * KVW + (ch - 512);
                *(__half2*)(base)                        = __floats2half2_rn(v00, v01);
                *(__half2*)(base + KVW)                  = __floats2half2_rn(w00, w01);
                *(__half2*)(base + (size_t)16 * KVW)     = __floats2half2_rn(v10, v11);
                *(__half2*)(base + (size_t)17 * KVW)     = __floats2half2_rn(w10, w11);
            }
            cm0 = fmaxf(cm0, fmaxf(fmaxf(v00, w00), fmaxf(v10, w10)));
            cm1 = fmaxf(cm1, fmaxf(fmaxf(v01, w01), fmaxf(v11, w11)));
        }
#pragma unroll
        for (int o = 4; o <= 16; o <<= 1) {
            cm0 = fmaxf(cm0, __shfl_xor_sync(0xffffffffu, cm0, o));
            cm1 = fmaxf(cm1, __shfl_xor_sync(0xffffffffu, cm1, o));
        }
        if (lane < 4) {
            atomicMaxF(&g_cmax[b * MCH + ch], cm0);
            atomicMaxF(&g_cmax[b * MCH + ch + 1], cm1);
        }
    }
}

// ---------------------------------------------------------------------------
// attention stage 1: raw masked logits. grid = 32*8*8 (b, h, slice).
// ---------------------------------------------------------------------------
__global__ __launch_bounds__(256) void logits_kernel(const int* __restrict__ gmask,
                                                     const int* __restrict__ tmask) {
    __shared__ float q_s[64];
    const int bid   = blockIdx.x;
    const int slice = bid & 7;
    const int h     = (bid >> 3) & 7;
    const int b     = bid >> 6;
    const int tid   = threadIdx.x;
    const int lane  = tid & 31;
    const int w     = tid >> 5;

    if (tid < 64) q_s[tid] = g_cmax[b * MCH + h * HDd + tid];
    __syncthreads();

    const float scale = 0.04419417382415922f;   // 1/sqrt(512)
    const int j0  = slice * 256;
    const int cnt = (slice == NSL - 1) ? 257 : 256;
    const __half* Yk = g_Yh + (size_t)b * Ll * KVW + h * HDd;
    float* lg = g_lg + (b * Hh + h) * LGS;

    for (int jj = w; jj < cnt; jj += 8) {
        const int j = j0 + jj;
        float k0f, k1f;
        if (j == 0) {
            k0f = g_cmax[b * MCH + 512 + h * HDd + 2 * lane];
            k1f = g_cmax[b * MCH + 512 + h * HDd + 2 * lane + 1];
        } else {
            int l = j - 1;
            const __half2* r = (const __half2*)(Yk + (size_t)l * KVW) + lane;
            __half2 kv = r[0];
            if (l > 0)      kv = __hmax2(kv, r[-(KVW / 2)]);
            if (l < Ll - 1) kv = __hmax2(kv, r[KVW / 2]);
            float2 kf = __half22float2(kv);
            k0f = kf.x; k1f = kf.y;
        }
        float p = q_s[2 * lane] * k0f + q_s[2 * lane + 1] * k1f;
#pragma unroll
        for (int o = 16; o; o >>= 1) p += __shfl_down_sync(0xffffffffu, p, o);
        if (lane == 0) {
            int mk = (j == 0) ? gmask[b] : tmask[b * Ll + (j - 1)];
            lg[j] = mk ? p * scale : -1e30f;
        }
    }
}

// ---------------------------------------------------------------------------
// attention stage 2: softmax in place, probs scaled by 1/sum and g_mask.
// ---------------------------------------------------------------------------
__global__ __launch_bounds__(256) void softmax_kernel(const int* __restrict__ gmask) {
    __shared__ float red[256];
    const int b   = blockIdx.x >> 3;
    const int h   = blockIdx.x & 7;
    const int tid = threadIdx.x;
    float* lg = g_lg + (b * Hh + h) * LGS;

    float lm = -1e30f;
    for (int j = tid; j < LGS; j += 256) lm = fmaxf(lm, lg[j]);
    red[tid] = lm;
    __syncthreads();
    for (int s = 128; s; s >>= 1) {
        if (tid < s) red[tid] = fmaxf(red[tid], red[tid + s]);
        __syncthreads();
    }
    const float mx = red[0];
    __syncthreads();

    float ls = 0.f;
    float ev[9];
    int nv = 0;
    for (int j = tid; j < LGS; j += 256) {
        float e = expf(lg[j] - mx);
        ev[nv++] = e;
        ls += e;
    }
    red[tid] = ls;
    __syncthreads();
    for (int s = 128; s; s >>= 1) {
        if (tid < s) red[tid] += red[tid + s];
        __syncthreads();
    }
    const float fac = (1.0f / red[0]) * (float)gmask[b];
    nv = 0;
    for (int j = tid; j < LGS; j += 256) lg[j] = ev[nv++] * fac;
}

// ---------------------------------------------------------------------------
// attention stage 3: weighted V sum partials. grid = 32*8*8 (b, h, slice)
// ---------------------------------------------------------------------------
__global__ __launch_bounds__(256) void vsum_kernel() {
    __shared__ float red[256];
    const int bid   = blockIdx.x;
    const int slice = bid & 7;
    const int h     = (bid >> 3) & 7;
    const int b     = bid >> 6;
    const int tid   = threadIdx.x;
    const int d     = tid & 63;
    const int grp   = tid >> 6;

    const int j0  = slice * 256;
    const int cnt = (slice == NSL - 1) ? 257 : 256;
    const __half* Yv = g_Yh + (size_t)b * Ll * KVW + 512 + h * HDd + d;
    const float* lg = g_lg + (b * Hh + h) * LGS;

    float acc = 0.f;
    for (int jj = grp; jj < cnt; jj += 4) {
        const int j = j0 + jj;
        float v;
        if (j == 0) {
            v = g_cmax[b * MCH + 1024 + h * HDd + d];
        } else {
            int l = j - 1;
            const __half* r = Yv + (size_t)l * KVW;
            __half hv = r[0];
            if (l > 0)      hv = __hmax(hv, r[-KVW]);
            if (l < Ll - 1) hv = __hmax(hv, r[KVW]);
            v = __half2float(hv);
        }
        acc += lg[j] * v;
    }
    red[tid] = acc;
    __syncthreads();
    if (tid < 64) {
        float o = red[tid] + red[tid + 64] + red[tid + 128] + red[tid + 192];
        g_part[((b * Hh + h) * NSL + slice) * HDd + d] = o;
    }
}

// ---------------------------------------------------------------------------
// final: reduce slice partials, head-mix (Wh 8x8), output 1x1 conv (Wo).
// ---------------------------------------------------------------------------
__global__ __launch_bounds__(512) void final_kernel(const float* __restrict__ Wh,
                                                    const float* __restrict__ bh,
                                                    const float* __restrict__ Wo,
                                                    const float* __restrict__ bo,
                                                    float* __restrict__ out) {
    const int b    = blockIdx.x;
    const int quad = blockIdx.y;
    const int tid  = threadIdx.x;
    __shared__ float att_s[512];
    __shared__ float mid[512];

    {
        const int h = tid >> 6, d = tid & 63;
        const float* p = g_part + ((b * Hh + h) * NSL) * HDd + d;
        float s = 0.f;
#pragma unroll
        for (int sl = 0; sl < NSL; sl++) s += p[sl * HDd];
        att_s[tid] = s;
    }
    __syncthreads();

    {
        const int oh = tid >> 6, d = tid & 63;
        float s = bh[oh];
#pragma unroll
        for (int i = 0; i < 8; i++) s += Wh[oh * 8 + i] * att_s[i * HDd + d];
        mid[tid] = s;
    }
    __syncthreads();

    const int o    = quad * 128 + (tid >> 2);
    const int part = tid & 3;
    const float* wr = Wo + (size_t)o * 512 + part * 128;
    const float* mr = mid + part * 128;
    float s = 0.f;
#pragma unroll 16
    for (int i = 0; i < 128; i++) s += wr[i] * mr[i];
    s += __shfl_xor_sync(0xffffffffu, s, 1);
    s += __shfl_xor_sync(0xffffffffu, s, 2);
    if (part == 0) out[b * 512 + o] = s + bo[o];
}

// ---------------------------------------------------------------------------
// Launch
// ---------------------------------------------------------------------------
extern "C" void kernel_launch(void* const* d_in, const int* in_sizes, int n_in,
                              void* d_out, int out_size) {
    const float* t     = (const float*)d_in[0];
    const int*   gmask = (const int*)d_in[2];
    const int*   tmask = (const int*)d_in[3];
    const float* Wq    = (const float*)d_in[4];
    const float* bq    = (const float*)d_in[5];
    const float* Wk    = (const float*)d_in[6];
    const float* bk    = (const float*)d_in[7];
    const float* Wv    = (const float*)d_in[8];
    const float* bv    = (const float*)d_in[9];
    const float* Wh    = (const float*)d_in[10];
    const float* bh    = (const float*)d_in[11];
    const float* Wo    = (const float*)d_in[12];
    const float* bo    = (const float*)d_in[13];
    float* out = (float*)d_out;

    cudaFuncSetAttribute(conv_wino_kernel, cudaFuncAttributeMaxDynamicSharedMemorySize,
                         NSTAGEW * STAGEW);

    vtrans_kernel<<<(NPAIR * 128 + 255) / 256, 256>>>(t);
    wtrans_kernel<<<(MCH * 512 + 255) / 256, 256>>>(Wq, bq, Wk, bk, Wv, bv);
    cmax_init_kernel<<<(Bb * MCH + 255) / 256, 256>>>();
    conv_wino_kernel<<<dim3(MCH / TNW, NPAIR / PB), 256, NSTAGEW * STAGEW>>>();
    logits_kernel<<<Bb * Hh * NSL, 256>>>(gmask, tmask);
    softmax_kernel<<<Bb * Hh, 256>>>(gmask);
    vsum_kernel<<<Bb * Hh * NSL, 256>>>();
    final_kernel<<<dim3(Bb, 4), 512>>>(Wh, bh, Wo, bo, out);
}

// round 8
// speedup vs baseline: 1.5119x; 1.2451x over previous
#include <cuda_runtime.h>
#include <cuda_fp16.h>
#include <cstdint>
#include <cstddef>

// Problem constants
#define Bb 32
#define Ll 2048
#define Uu 512
#define Hh 8
#define HDd 64
#define NPOS (Bb * Ll)      // 65536
#define MCH 1536            // q|k|v channels (cmax indexing)
#define KVW 1024            // stored channels (k,v only), fp16
#define LGS 2049            // logits per (b,h)
#define NSL 8               // attention slices
#define NPAIR 32768         // Winograd output pairs (NPOS/2)

// Winograd GEMM config: M = pairs, N = channels, K = 512 per g, 4 g's
#define PB 128              // pairs per block tile
#define TNW 128             // channels per block tile
#define BKW 64
#define NCHUNKW 32          // 4 g * (512/64)
#define A_BYTES_W 16384     // 128 pairs * 64 k * 2B
#define B_BYTES_W 16384     // 128 ch * 64 k * 2B
#define STAGEW 32768
#define NSTAGEW 3

// ---------------------------------------------------------------------------
// Device scratch
// ---------------------------------------------------------------------------
__device__ __align__(16) __half g_V[4ull * NPAIR * 512];      // Winograd inputs, 128MB
__device__ __align__(16) __half g_U[4ull * MCH * 512];        // Winograd weights, 6MB
__device__ __align__(16) __half g_Yh[(size_t)NPOS * KVW];     // k|v conv out fp16, 128MB
__device__ float g_bias[MCH];
__device__ float g_cmax[Bb * MCH];
__device__ float g_lg[Bb * Hh * LGS];                         // logits -> probs
__device__ float g_part[Bb * Hh * NSL * HDd];                 // V partial sums

// ---------------------------------------------------------------------------
// Helpers
// ---------------------------------------------------------------------------
__device__ __forceinline__ void cp16(uint32_t dst, const void* src) {
    asm volatile("cp.async.cg.shared.global [%0], [%1], 16;\n"
                 :: "r"(dst), "l"(src));
}
#define CP_COMMIT() asm volatile("cp.async.commit_group;" ::: "memory")
#define CP_WAIT(n)  asm volatile("cp.async.wait_group %0;" :: "n"(n) : "memory")

__device__ __forceinline__ uint32_t su32(const void* p) {
    uint32_t a;
    asm("{ .reg .u64 t; cvta.to.shared.u64 t, %1; cvt.u32.u64 %0, t; }" : "=r"(a) : "l"(p));
    return a;
}

__device__ __forceinline__ void mma_f16(float c[4],
                                        uint32_t a0, uint32_t a1, uint32_t a2, uint32_t a3,
                                        uint32_t b0, uint32_t b1) {
    asm volatile(
        "mma.sync.aligned.m16n8k16.row.col.f32.f16.f16.f32 "
        "{%0,%1,%2,%3}, {%4,%5,%6,%7}, {%8,%9}, {%0,%1,%2,%3};\n"
        : "+f"(c[0]), "+f"(c[1]), "+f"(c[2]), "+f"(c[3])
        : "r"(a0), "r"(a1), "r"(a2), "r"(a3), "r"(b0), "r"(b1));
}

#define LDSM_X4(r0, r1, r2, r3, addr)                                         \
    asm volatile("ldmatrix.sync.aligned.m8n8.x4.shared.b16 {%0,%1,%2,%3}, [%4];" \
                 : "=r"(r0), "=r"(r1), "=r"(r2), "=r"(r3) : "r"(addr))

__device__ __forceinline__ void atomicMaxF(float* a, float v) {
    if (v >= 0.f) atomicMax((int*)a, __float_as_int(v));
    else          atomicMin((unsigned*)a, __float_as_uint(v));
}

// ---------------------------------------------------------------------------
// Winograd input transform: t(float) -> 4 fp16 arrays V_g[pair][512]
// ---------------------------------------------------------------------------
__global__ __launch_bounds__(256) void vtrans_kernel(const float* __restrict__ t) {
    int gid = blockIdx.x * 256 + threadIdx.x;        // NPAIR * 128
    if (gid >= NPAIR * 128) return;
    const int pair = gid >> 7;
    const int cg   = (gid & 127) << 2;
    const int lp   = pair & 1023;
    const float* base = t + ((size_t)pair * 2) * Uu + cg;   // x[2p] row (global)

    float4 w1 = *(const float4*)(base);
    float4 w2 = *(const float4*)(base + Uu);
    float4 w0 = make_float4(0.f, 0.f, 0.f, 0.f);
    float4 w3 = make_float4(0.f, 0.f, 0.f, 0.f);
    if (lp > 0)    w0 = *(const float4*)(base - Uu);
    if (lp < 1023) w3 = *(const float4*)(base + 2 * Uu);

    const size_t eo = (size_t)pair * 512 + cg;
    auto st = [&](int g, float a, float b, float c, float d) {
        __half2 lo = __floats2half2_rn(a, b);
        __half2 hi = __floats2half2_rn(c, d);
        *(uint2*)(g_V + (size_t)g * NPAIR * 512 + eo) =
            make_uint2(*(uint32_t*)&lo, *(uint32_t*)&hi);
    };
    st(0, w0.x - w2.x, w0.y - w2.y, w0.z - w2.z, w0.w - w2.w);
    st(1, w1.x + w2.x, w1.y + w2.y, w1.z + w2.z, w1.w + w2.w);
    st(2, w2.x - w1.x, w2.y - w1.y, w2.z - w1.z, w2.w - w1.w);
    st(3, w1.x - w3.x, w1.y - w3.y, w1.z - w3.z, w1.w - w3.w);
}

// ---------------------------------------------------------------------------
// Winograd weight transform
// ---------------------------------------------------------------------------
__global__ __launch_bounds__(256) void wtrans_kernel(
        const float* __restrict__ Wq, const float* __restrict__ bq,
        const float* __restrict__ Wk, const float* __restrict__ bk,
        const float* __restrict__ Wv, const float* __restrict__ bv) {
    int gid = blockIdx.x * 256 + threadIdx.x;
    if (gid < MCH)
        g_bias[gid] = gid < 512 ? bq[gid] : (gid < 1024 ? bk[gid - 512] : bv[gid - 1024]);
    if (gid >= MCH * 512) return;
    const int mg = gid / 512;
    const int k  = gid % 512;
    const int conv = mg / 512;
    const int m    = mg % 512;
    const float* W = (conv == 0) ? Wq : ((conv == 1) ? Wk : Wv);
    const float g0 = W[m * 1536 + k * 3 + 0];
    const float g1 = W[m * 1536 + k * 3 + 1];
    const float g2 = W[m * 1536 + k * 3 + 2];
    const size_t eo = (size_t)mg * 512 + k;
    g_U[0ull * MCH * 512 + eo] = __float2half_rn(g0);
    g_U[1ull * MCH * 512 + eo] = __float2half_rn(0.5f * (g0 + g1 + g2));
    g_U[2ull * MCH * 512 + eo] = __float2half_rn(0.5f * (g0 - g1 + g2));
    g_U[3ull * MCH * 512 + eo] = __float2half_rn(g2);
}

__global__ void cmax_init_kernel() {
    int gid = blockIdx.x * blockDim.x + threadIdx.x;
    if (gid < Bb * MCH) ((unsigned*)g_cmax)[gid] = 0xff800000u;   // -inf
}

// ---------------------------------------------------------------------------
// Winograd conv GEMM: 128 pairs x 128 channels per block, 8 warps,
// warp tile 64 pairs x 32 ch, ldmatrix fragment loads, 3-stage cp.async.
// m_g accumulated per g, folded into y0/y1 with A^T coefficients.
// ---------------------------------------------------------------------------
__global__ __launch_bounds__(256, 1) void conv_wino_kernel() {
    extern __shared__ __align__(128) char dsmem[];   // 3 * 32KB
    __shared__ float bias_s[TNW];

    const int tid  = threadIdx.x;
    const int wid  = tid >> 5;
    const int lane = tid & 31;
    const int gr   = lane >> 2;
    const int tg   = lane & 3;
    const int wp   = wid & 1;           // 2 warps over pairs (64 each)
    const int wc   = wid >> 1;          // 4 warps over channels (32 each)
    const int m0    = blockIdx.x * TNW;
    const int pair0 = blockIdx.y * PB;
    const int b     = pair0 >> 10;

    if (tid < TNW) bias_s[tid] = g_bias[m0 + tid];

    const uint32_t smem0 = su32(dsmem);

    auto load_chunk = [&](int c, int slot) {
        const int g  = c >> 3;
        const int k0 = (c & 7) * BKW;
        const uint32_t abase = smem0 + (uint32_t)slot * STAGEW;
        const uint32_t bbase = abase + A_BYTES_W;
#pragma unroll
        for (int p = 0; p < 4; p++) {           // A: 128 rows x 8 chunks
            int idx = p * 256 + tid;
            int row = idx >> 3;
            int j   = idx & 7;
            const void* src = g_V + (size_t)g * NPAIR * 512
                              + (size_t)(pair0 + row) * 512 + k0 + j * 8;
            cp16(abase + (uint32_t)(row * 128 + ((j ^ (row & 7)) << 4)), src);
        }
#pragma unroll
        for (int p = 0; p < 4; p++) {           // B: 128 rows x 8 chunks
            int idx = p * 256 + tid;
            int row = idx >> 3;
            int j   = idx & 7;
            const void* src = g_U + (size_t)g * MCH * 512
                              + (size_t)(m0 + row) * 512 + k0 + j * 8;
            cp16(bbase + (uint32_t)(row * 128 + ((j ^ (row & 7)) << 4)), src);
        }
    };

    // ldmatrix per-lane row offsets (swizzle mask reduces to lr for 16-multiple bases)
    const int sub = lane >> 3;          // 0..3
    const int lr  = lane & 7;
    uint32_t aRowOff[4], bRowOff[2];
#pragma unroll
    for (int mt = 0; mt < 4; mt++)
        aRowOff[mt] = (uint32_t)((wp * 64 + mt * 16 + ((sub & 1) << 3) + lr) * 128);
#pragma unroll
    for (int p = 0; p < 2; p++)
        bRowOff[p] = (uint32_t)((wc * 32 + p * 16 + ((sub >> 1) << 3) + lr) * 128);
    const int aSub = sub >> 1;
    const int bSub = sub & 1;

    float y0[4][4][4], y1[4][4][4], macc[4][4][4];
#pragma unroll
    for (int i = 0; i < 4; i++)
#pragma unroll
        for (int j = 0; j < 4; j++)
#pragma unroll
            for (int e = 0; e < 4; e++) { y0[i][j][e] = 0.f; y1[i][j][e] = 0.f; macc[i][j][e] = 0.f; }

    load_chunk(0, 0); CP_COMMIT();
    load_chunk(1, 1); CP_COMMIT();

    for (int c = 0; c < NCHUNKW; c++) {
        if (c + 1 < NCHUNKW) { CP_WAIT(1); } else { CP_WAIT(0); }
        __syncthreads();
        if (c + 2 < NCHUNKW) { load_chunk(c + 2, (c + 2) % NSTAGEW); CP_COMMIT(); }

        const uint32_t abase = smem0 + (uint32_t)(c % NSTAGEW) * STAGEW;
        const uint32_t bbase = abase + A_BYTES_W;
#pragma unroll
        for (int kk = 0; kk < 4; kk++) {
            const uint32_t aCh = (uint32_t)(((2 * kk + aSub) ^ lr) << 4);
            const uint32_t bCh = (uint32_t)(((2 * kk + bSub) ^ lr) << 4);
            uint32_t a[4][4];
#pragma unroll
            for (int mt = 0; mt < 4; mt++)
                LDSM_X4(a[mt][0], a[mt][1], a[mt][2], a[mt][3],
                        abase + aRowOff[mt] + aCh);
            uint32_t bf[4][2];
#pragma unroll
            for (int p = 0; p < 2; p++)
                LDSM_X4(bf[2 * p][0], bf[2 * p][1], bf[2 * p + 1][0], bf[2 * p + 1][1],
                        bbase + bRowOff[p] + bCh);
#pragma unroll
            for (int mt = 0; mt < 4; mt++)
#pragma unroll
                for (int nt = 0; nt < 4; nt++)
                    mma_f16(macc[mt][nt], a[mt][0], a[mt][1], a[mt][2], a[mt][3],
                            bf[nt][0], bf[nt][1]);
        }

        if ((c & 7) == 7) {             // end of g: fold m into y (A^T coeffs)
            const int g = c >> 3;
            const float c0 = (g < 3) ? 1.f : 0.f;                       // y0: m0+m1+m2
            const float c1 = (g == 1) ? 1.f : ((g >= 2) ? -1.f : 0.f);  // y1: m1-m2-m3
#pragma unroll
            for (int mt = 0; mt < 4; mt++)
#pragma unroll
                for (int nt = 0; nt < 4; nt++)
#pragma unroll
                    for (int e = 0; e < 4; e++) {
                        y0[mt][nt][e] += c0 * macc[mt][nt][e];
                        y1[mt][nt][e] += c1 * macc[mt][nt][e];
                        macc[mt][nt][e] = 0.f;
                    }
        }
    }

    // ---- epilogue: bias, channel max, fp16 k/v store ----
    const bool do_store = (m0 >= 512);
#pragma unroll
    for (int nt = 0; nt < 4; nt++) {
        const int ch = m0 + wc * 32 + nt * 8 + 2 * tg;
        const float b0 = bias_s[ch - m0], b1 = bias_s[ch - m0 + 1];
        float cm0 = -3.4e38f, cm1 = -3.4e38f;
#pragma unroll
        for (int mt = 0; mt < 4; mt++) {
            const int P = pair0 + wp * 64 + mt * 16 + gr;
            float v00 = y0[mt][nt][0] + b0, v01 = y0[mt][nt][1] + b1;   // Y[2P]
            float w00 = y1[mt][nt][0] + b0, w01 = y1[mt][nt][1] + b1;   // Y[2P+1]
            float v10 = y0[mt][nt][2] + b0, v11 = y0[mt][nt][3] + b1;   // Y[2(P+8)]
            float w10 = y1[mt][nt][2] + b0, w11 = y1[mt][nt][3] + b1;   // Y[2(P+8)+1]
            if (do_store) {
                __half* base = g_Yh + (size_t)(2 * P) * KVW + (ch - 512);
                *(__half2*)(base)                    = __floats2half2_rn(v00, v01);
                *(__half2*)(base + KVW)              = __floats2half2_rn(w00, w01);
                *(__half2*)(base + (size_t)16 * KVW) = __floats2half2_rn(v10, v11);
                *(__half2*)(base + (size_t)17 * KVW) = __floats2half2_rn(w10, w11);
            }
            cm0 = fmaxf(cm0, fmaxf(fmaxf(v00, w00), fmaxf(v10, w10)));
            cm1 = fmaxf(cm1, fmaxf(fmaxf(v01, w01), fmaxf(v11, w11)));
        }
#pragma unroll
        for (int o = 4; o <= 16; o <<= 1) {
            cm0 = fmaxf(cm0, __shfl_xor_sync(0xffffffffu, cm0, o));
            cm1 = fmaxf(cm1, __shfl_xor_sync(0xffffffffu, cm1, o));
        }
        if (lane < 4) {
            atomicMaxF(&g_cmax[b * MCH + ch], cm0);
            atomicMaxF(&g_cmax[b * MCH + ch + 1], cm1);
        }
    }
}

// ---------------------------------------------------------------------------
// attention stage 1: raw masked logits. grid = 32*8*8 (b, h, slice).
// ---------------------------------------------------------------------------
__global__ __launch_bounds__(256) void logits_kernel(const int* __restrict__ gmask,
                                                     const int* __restrict__ tmask) {
    __shared__ float q_s[64];
    const int bid   = blockIdx.x;
    const int slice = bid & 7;
    const int h     = (bid >> 3) & 7;
    const int b     = bid >> 6;
    const int tid   = threadIdx.x;
    const int lane  = tid & 31;
    const int w     = tid >> 5;

    if (tid < 64) q_s[tid] = g_cmax[b * MCH + h * HDd + tid];
    __syncthreads();

    const float scale = 0.04419417382415922f;   // 1/sqrt(512)
    const int j0  = slice * 256;
    const int cnt = (slice == NSL - 1) ? 257 : 256;
    const __half* Yk = g_Yh + (size_t)b * Ll * KVW + h * HDd;
    float* lg = g_lg + (b * Hh + h) * LGS;

    for (int jj = w; jj < cnt; jj += 8) {
        const int j = j0 + jj;
        float k0f, k1f;
        if (j == 0) {
            k0f = g_cmax[b * MCH + 512 + h * HDd + 2 * lane];
            k1f = g_cmax[b * MCH + 512 + h * HDd + 2 * lane + 1];
        } else {
            int l = j - 1;
            const __half2* r = (const __half2*)(Yk + (size_t)l * KVW) + lane;
            __half2 kv = r[0];
            if (l > 0)      kv = __hmax2(kv, r[-(KVW / 2)]);
            if (l < Ll - 1) kv = __hmax2(kv, r[KVW / 2]);
            float2 kf = __half22float2(kv);
            k0f = kf.x; k1f = kf.y;
        }
        float p = q_s[2 * lane] * k0f + q_s[2 * lane + 1] * k1f;
#pragma unroll
        for (int o = 16; o; o >>= 1) p += __shfl_down_sync(0xffffffffu, p, o);
        if (lane == 0) {
            int mk = (j == 0) ? gmask[b] : tmask[b * Ll + (j - 1)];
            lg[j] = mk ? p * scale : -1e30f;
        }
    }
}

// ---------------------------------------------------------------------------
// attention stage 2: softmax in place, probs scaled by 1/sum and g_mask.
// ---------------------------------------------------------------------------
__global__ __launch_bounds__(256) void softmax_kernel(const int* __restrict__ gmask) {
    __shared__ float red[256];
    const int b   = blockIdx.x >> 3;
    const int h   = blockIdx.x & 7;
    const int tid = threadIdx.x;
    float* lg = g_lg + (b * Hh + h) * LGS;

    float lm = -1e30f;
    for (int j = tid; j < LGS; j += 256) lm = fmaxf(lm, lg[j]);
    red[tid] = lm;
    __syncthreads();
    for (int s = 128; s; s >>= 1) {
        if (tid < s) red[tid] = fmaxf(red[tid], red[tid + s]);
        __syncthreads();
    }
    const float mx = red[0];
    __syncthreads();

    float ls = 0.f;
    float ev[9];
    int nv = 0;
    for (int j = tid; j < LGS; j += 256) {
        float e = expf(lg[j] - mx);
        ev[nv++] = e;
        ls += e;
    }
    red[tid] = ls;
    __syncthreads();
    for (int s = 128; s; s >>= 1) {
        if (tid < s) red[tid] += red[tid + s];
        __syncthreads();
    }
    const float fac = (1.0f / red[0]) * (float)gmask[b];
    nv = 0;
    for (int j = tid; j < LGS; j += 256) lg[j] = ev[nv++] * fac;
}

// ---------------------------------------------------------------------------
// attention stage 3: weighted V sum partials. grid = 32*8*8 (b, h, slice)
// ---------------------------------------------------------------------------
__global__ __launch_bounds__(256) void vsum_kernel() {
    __shared__ float red[256];
    const int bid   = blockIdx.x;
    const int slice = bid & 7;
    const int h     = (bid >> 3) & 7;
    const int b     = bid >> 6;
    const int tid   = threadIdx.x;
    const int d     = tid & 63;
    const int grp   = tid >> 6;

    const int j0  = slice * 256;
    const int cnt = (slice == NSL - 1) ? 257 : 256;
    const __half* Yv = g_Yh + (size_t)b * Ll * KVW + 512 + h * HDd + d;
    const float* lg = g_lg + (b * Hh + h) * LGS;

    float acc = 0.f;
    for (int jj = grp; jj < cnt; jj += 4) {
        const int j = j0 + jj;
        float v;
        if (j == 0) {
            v = g_cmax[b * MCH + 1024 + h * HDd + d];
        } else {
            int l = j - 1;
            const __half* r = Yv + (size_t)l * KVW;
            __half hv = r[0];
            if (l > 0)      hv = __hmax(hv, r[-KVW]);
            if (l < Ll - 1) hv = __hmax(hv, r[KVW]);
            v = __half2float(hv);
        }
        acc += lg[j] * v;
    }
    red[tid] = acc;
    __syncthreads();
    if (tid < 64) {
        float o = red[tid] + red[tid + 64] + red[tid + 128] + red[tid + 192];
        g_part[((b * Hh + h) * NSL + slice) * HDd + d] = o;
    }
}

// ---------------------------------------------------------------------------
// final: reduce slice partials, head-mix (Wh 8x8), output 1x1 conv (Wo).
// ---------------------------------------------------------------------------
__global__ __launch_bounds__(512) void final_kernel(const float* __restrict__ Wh,
                                                    const float* __restrict__ bh,
                                                    const float* __restrict__ Wo,
                                                    const float* __restrict__ bo,
                                                    float* __restrict__ out) {
    const int b    = blockIdx.x;
    const int quad = blockIdx.y;
    const int tid  = threadIdx.x;
    __shared__ float att_s[512];
    __shared__ float mid[512];

    {
        const int h = tid >> 6, d = tid & 63;
        const float* p = g_part + ((b * Hh + h) * NSL) * HDd + d;
        float s = 0.f;
#pragma unroll
        for (int sl = 0; sl < NSL; sl++) s += p[sl * HDd];
        att_s[tid] = s;
    }
    __syncthreads();

    {
        const int oh = tid >> 6, d = tid & 63;
        float s = bh[oh];
#pragma unroll
        for (int i = 0; i < 8; i++) s += Wh[oh * 8 + i] * att_s[i * HDd + d];
        mid[tid] = s;
    }
    __syncthreads();

    const int o    = quad * 128 + (tid >> 2);
    const int part = tid & 3;
    const float* wr = Wo + (size_t)o * 512 + part * 128;
    const float* mr = mid + part * 128;
    float s = 0.f;
#pragma unroll 16
    for (int i = 0; i < 128; i++) s += wr[i] * mr[i];
    s += __shfl_xor_sync(0xffffffffu, s, 1);
    s += __shfl_xor_sync(0xffffffffu, s, 2);
    if (part == 0) out[b * 512 + o] = s + bo[o];
}

// ---------------------------------------------------------------------------
// Launch
// ---------------------------------------------------------------------------
extern "C" void kernel_launch(void* const* d_in, const int* in_sizes, int n_in,
                              void* d_out, int out_size) {
    const float* t     = (const float*)d_in[0];
    const int*   gmask = (const int*)d_in[2];
    const int*   tmask = (const int*)d_in[3];
    const float* Wq    = (const float*)d_in[4];
    const float* bq    = (const float*)d_in[5];
    const float* Wk    = (const float*)d_in[6];
    const float* bk    = (const float*)d_in[7];
    const float* Wv    = (const float*)d_in[8];
    const float* bv    = (const float*)d_in[9];
    const float* Wh    = (const float*)d_in[10];
    const float* bh    = (const float*)d_in[11];
    const float* Wo    = (const float*)d_in[12];
    const float* bo    = (const float*)d_in[13];
    float* out = (float*)d_out;

    cudaFuncSetAttribute(conv_wino_kernel, cudaFuncAttributeMaxDynamicSharedMemorySize,
                         NSTAGEW * STAGEW);

    vtrans_kernel<<<(NPAIR * 128 + 255) / 256, 256>>>(t);
    wtrans_kernel<<<(MCH * 512 + 255) / 256, 256>>>(Wq, bq, Wk, bk, Wv, bv);
    cmax_init_kernel<<<(Bb * MCH + 255) / 256, 256>>>();
    conv_wino_kernel<<<dim3(MCH / TNW, NPAIR / PB), 256, NSTAGEW * STAGEW>>>();
    logits_kernel<<<Bb * Hh * NSL, 256>>>(gmask, tmask);
    softmax_kernel<<<Bb * Hh, 256>>>(gmask);
    vsum_kernel<<<Bb * Hh * NSL, 256>>>();
    final_kernel<<<dim3(Bb, 4), 512>>>(Wh, bh, Wo, bo, out);
}

// round 9
// speedup vs baseline: 1.6311x; 1.0788x over previous
#include <cuda_runtime.h>
#include <cuda_fp16.h>
#include <cstdint>
#include <cstddef>

// Problem constants
#define Bb 32
#define Ll 2048
#define Uu 512
#define Hh 8
#define HDd 64
#define NPOS (Bb * Ll)      // 65536
#define MCH 1536            // q|k|v channels (cmax indexing)
#define KVW 1024            // stored channels (k,v only), fp16
#define LGS 2049            // logits per (b,h)
#define NSL 8               // attention slices
#define NPAIR 32768         // Winograd output pairs (NPOS/2)

// Winograd GEMM config: M = pairs, N = channels, K = 512 per g, 4 g's
#define PB 128              // pairs per block tile
#define TNW 128             // channels per block tile
#define BKW 64
#define NSUPER 16           // superchunks (2 k-chunks each)
#define TILE16K 16384
#define STAGEW 65536        // [A0|B0|A1|B1]
#define NSTAGEW 3           // 192KB total

// ---------------------------------------------------------------------------
// Device scratch
// ---------------------------------------------------------------------------
__device__ __align__(16) __half g_V[4ull * NPAIR * 512];      // Winograd inputs, 128MB
__device__ __align__(16) __half g_U[4ull * MCH * 512];        // Winograd weights (U3 negated)
__device__ __align__(16) __half g_Yh[(size_t)NPOS * KVW];     // k|v conv out fp16, 128MB
__device__ float g_bias[MCH];
__device__ float g_cmax[Bb * MCH];
__device__ float g_lg[Bb * Hh * LGS];                         // logits -> probs
__device__ float g_part[Bb * Hh * NSL * HDd];                 // V partial sums

// ---------------------------------------------------------------------------
// Helpers
// ---------------------------------------------------------------------------
__device__ __forceinline__ void cp16(uint32_t dst, const void* src) {
    asm volatile("cp.async.cg.shared.global [%0], [%1], 16;\n"
                 :: "r"(dst), "l"(src));
}
#define CP_COMMIT() asm volatile("cp.async.commit_group;" ::: "memory")
#define CP_WAIT(n)  asm volatile("cp.async.wait_group %0;" :: "n"(n) : "memory")

__device__ __forceinline__ uint32_t su32(const void* p) {
    uint32_t a;
    asm("{ .reg .u64 t; cvta.to.shared.u64 t, %1; cvt.u32.u64 %0, t; }" : "=r"(a) : "l"(p));
    return a;
}

__device__ __forceinline__ void mma_f16(float c[4],
                                        uint32_t a0, uint32_t a1, uint32_t a2, uint32_t a3,
                                        uint32_t b0, uint32_t b1) {
    asm volatile(
        "mma.sync.aligned.m16n8k16.row.col.f32.f16.f16.f32 "
        "{%0,%1,%2,%3}, {%4,%5,%6,%7}, {%8,%9}, {%0,%1,%2,%3};\n"
        : "+f"(c[0]), "+f"(c[1]), "+f"(c[2]), "+f"(c[3])
        : "r"(a0), "r"(a1), "r"(a2), "r"(a3), "r"(b0), "r"(b1));
}

#define LDSM_X4(r0, r1, r2, r3, addr)                                         \
    asm volatile("ldmatrix.sync.aligned.m8n8.x4.shared.b16 {%0,%1,%2,%3}, [%4];" \
                 : "=r"(r0), "=r"(r1), "=r"(r2), "=r"(r3) : "r"(addr))

__device__ __forceinline__ void atomicMaxF(float* a, float v) {
    if (v >= 0.f) atomicMax((int*)a, __float_as_int(v));
    else          atomicMin((unsigned*)a, __float_as_uint(v));
}

// ---------------------------------------------------------------------------
// Winograd input transform: t(float) -> 4 fp16 arrays V_g[pair][512]
// ---------------------------------------------------------------------------
__global__ __launch_bounds__(256) void vtrans_kernel(const float* __restrict__ t) {
    int gid = blockIdx.x * 256 + threadIdx.x;        // NPAIR * 128
    if (gid >= NPAIR * 128) return;
    const int pair = gid >> 7;
    const int cg   = (gid & 127) << 2;
    const int lp   = pair & 1023;
    const float* base = t + ((size_t)pair * 2) * Uu + cg;   // x[2p] row (global)

    float4 w1 = *(const float4*)(base);
    float4 w2 = *(const float4*)(base + Uu);
    float4 w0 = make_float4(0.f, 0.f, 0.f, 0.f);
    float4 w3 = make_float4(0.f, 0.f, 0.f, 0.f);
    if (lp > 0)    w0 = *(const float4*)(base - Uu);
    if (lp < 1023) w3 = *(const float4*)(base + 2 * Uu);

    const size_t eo = (size_t)pair * 512 + cg;
    auto st = [&](int g, float a, float b, float c, float d) {
        __half2 lo = __floats2half2_rn(a, b);
        __half2 hi = __floats2half2_rn(c, d);
        *(uint2*)(g_V + (size_t)g * NPAIR * 512 + eo) =
            make_uint2(*(uint32_t*)&lo, *(uint32_t*)&hi);
    };
    st(0, w0.x - w2.x, w0.y - w2.y, w0.z - w2.z, w0.w - w2.w);
    st(1, w1.x + w2.x, w1.y + w2.y, w1.z + w2.z, w1.w + w2.w);
    st(2, w2.x - w1.x, w2.y - w1.y, w2.z - w1.z, w2.w - w1.w);
    st(3, w1.x - w3.x, w1.y - w3.y, w1.z - w3.z, w1.w - w3.w);
}

// ---------------------------------------------------------------------------
// Winograd weight transform (U3 stored NEGATED so g3 mma's directly into y1).
// Also: bias fill + cmax init (merged).
// ---------------------------------------------------------------------------
__global__ __launch_bounds__(256) void wtrans_kernel(
        const float* __restrict__ Wq, const float* __restrict__ bq,
        const float* __restrict__ Wk, const float* __restrict__ bk,
        const float* __restrict__ Wv, const float* __restrict__ bv) {
    int gid = blockIdx.x * 256 + threadIdx.x;
    if (gid < MCH)
        g_bias[gid] = gid < 512 ? bq[gid] : (gid < 1024 ? bk[gid - 512] : bv[gid - 1024]);
    if (gid < Bb * MCH) ((unsigned*)g_cmax)[gid] = 0xff800000u;   // -inf
    if (gid >= MCH * 512) return;
    const int mg = gid / 512;
    const int k  = gid % 512;
    const int conv = mg / 512;
    const int m    = mg % 512;
    const float* W = (conv == 0) ? Wq : ((conv == 1) ? Wk : Wv);
    const float g0 = W[m * 1536 + k * 3 + 0];
    const float g1 = W[m * 1536 + k * 3 + 1];
    const float g2 = W[m * 1536 + k * 3 + 2];
    const size_t eo = (size_t)mg * 512 + k;
    g_U[0ull * MCH * 512 + eo] = __float2half_rn(g0);
    g_U[1ull * MCH * 512 + eo] = __float2half_rn(0.5f * (g0 + g1 + g2));
    g_U[2ull * MCH * 512 + eo] = __float2half_rn(0.5f * (g0 - g1 + g2));
    g_U[3ull * MCH * 512 + eo] = __float2half_rn(-g2);           // NEGATED
}

// ---------------------------------------------------------------------------
// Winograd conv GEMM: 128 pairs x 128 channels per block, 8 warps,
// warp tile 64 pairs x 32 ch, ldmatrix loads, 3-stage x 2-chunk pipeline.
// g0 -> y0 direct, g1/g2 -> macc (+fold), g3 -> y1 direct (U3 negated).
// ---------------------------------------------------------------------------
__global__ __launch_bounds__(256, 1) void conv_wino_kernel() {
    extern __shared__ __align__(128) char dsmem[];   // 3 * 64KB
    __shared__ float bias_s[TNW];

    const int tid  = threadIdx.x;
    const int wid  = tid >> 5;
    const int lane = tid & 31;
    const int gr   = lane >> 2;
    const int tg   = lane & 3;
    const int wp   = wid & 1;           // 2 warps over pairs (64 each)
    const int wc   = wid >> 1;          // 4 warps over channels (32 each)
    const int m0    = blockIdx.x * TNW;
    const int pair0 = blockIdx.y * PB;
    const int b     = pair0 >> 10;

    if (tid < TNW) bias_s[tid] = g_bias[m0 + tid];

    const uint32_t smem0 = su32(dsmem);

    // load one k-chunk (A 16KB + B 16KB) at the given smem base
    auto load_chunk = [&](int c, uint32_t cbase) {
        const int g  = c >> 3;
        const int k0 = (c & 7) * BKW;
#pragma unroll
        for (int p = 0; p < 4; p++) {           // A: 128 rows x 8 chunks
            int idx = p * 256 + tid;
            int row = idx >> 3;
            int j   = idx & 7;
            const void* src = g_V + (size_t)g * NPAIR * 512
                              + (size_t)(pair0 + row) * 512 + k0 + j * 8;
            cp16(cbase + (uint32_t)(row * 128 + ((j ^ (row & 7)) << 4)), src);
        }
#pragma unroll
        for (int p = 0; p < 4; p++) {           // B: 128 rows x 8 chunks
            int idx = p * 256 + tid;
            int row = idx >> 3;
            int j   = idx & 7;
            const void* src = g_U + (size_t)g * MCH * 512
                              + (size_t)(m0 + row) * 512 + k0 + j * 8;
            cp16(cbase + TILE16K + (uint32_t)(row * 128 + ((j ^ (row & 7)) << 4)), src);
        }
    };
    auto load_super = [&](int s, int slot) {
        const uint32_t base = smem0 + (uint32_t)slot * STAGEW;
        load_chunk(2 * s,     base);
        load_chunk(2 * s + 1, base + 2u * TILE16K);
    };

    // ldmatrix per-lane row offsets
    const int sub = lane >> 3;          // 0..3
    const int lr  = lane & 7;
    uint32_t aRowOff[4], bRowOff[2];
#pragma unroll
    for (int mt = 0; mt < 4; mt++)
        aRowOff[mt] = (uint32_t)((wp * 64 + mt * 16 + ((sub & 1) << 3) + lr) * 128);
#pragma unroll
    for (int p = 0; p < 2; p++)
        bRowOff[p] = (uint32_t)((wc * 32 + p * 16 + ((sub >> 1) << 3) + lr) * 128);
    const int aSub = sub >> 1;
    const int bSub = sub & 1;

    float y0[4][4][4], y1[4][4][4], macc[4][4][4];
#pragma unroll
    for (int i = 0; i < 4; i++)
#pragma unroll
        for (int j = 0; j < 4; j++)
#pragma unroll
            for (int e = 0; e < 4; e++) { y0[i][j][e] = 0.f; y1[i][j][e] = 0.f; macc[i][j][e] = 0.f; }

    // one 64-K compute phase (A tile at abase, B tile at abase+16KB) into acc
    auto compute_phase = [&](uint32_t abase, float (&acc)[4][4][4]) {
        const uint32_t bbase = abase + TILE16K;
#pragma unroll
        for (int kk = 0; kk < 4; kk++) {
            const uint32_t aCh = (uint32_t)(((2 * kk + aSub) ^ lr) << 4);
            const uint32_t bCh = (uint32_t)(((2 * kk + bSub) ^ lr) << 4);
            uint32_t a[4][4];
#pragma unroll
            for (int mt = 0; mt < 4; mt++)
                LDSM_X4(a[mt][0], a[mt][1], a[mt][2], a[mt][3],
                        abase + aRowOff[mt] + aCh);
            uint32_t bf[4][2];
#pragma unroll
            for (int p = 0; p < 2; p++)
                LDSM_X4(bf[2 * p][0], bf[2 * p][1], bf[2 * p + 1][0], bf[2 * p + 1][1],
                        bbase + bRowOff[p] + bCh);
#pragma unroll
            for (int mt = 0; mt < 4; mt++)
#pragma unroll
                for (int nt = 0; nt < 4; nt++)
                    mma_f16(acc[mt][nt], a[mt][0], a[mt][1], a[mt][2], a[mt][3],
                            bf[nt][0], bf[nt][1]);
        }
    };

    load_super(0, 0); CP_COMMIT();
    load_super(1, 1); CP_COMMIT();

    for (int s = 0; s < NSUPER; s++) {
        if (s + 1 < NSUPER) { CP_WAIT(1); } else { CP_WAIT(0); }
        __syncthreads();
        if (s + 2 < NSUPER) { load_super(s + 2, (s + 2) % NSTAGEW); CP_COMMIT(); }

        const uint32_t base = smem0 + (uint32_t)(s % NSTAGEW) * STAGEW;
        const int g = s >> 2;
        if (g == 0) {
            compute_phase(base, y0);
            compute_phase(base + 2u * TILE16K, y0);
        } else if (g == 1) {
            compute_phase(base, macc);
            compute_phase(base + 2u * TILE16K, macc);
            if (s == 7) {        // fold m1: y0 += m1, y1 += m1
#pragma unroll
                for (int mt = 0; mt < 4; mt++)
#pragma unroll
                    for (int nt = 0; nt < 4; nt++)
#pragma unroll
                        for (int e = 0; e < 4; e++) {
                            y0[mt][nt][e] += macc[mt][nt][e];
                            y1[mt][nt][e] += macc[mt][nt][e];
                            macc[mt][nt][e] = 0.f;
                        }
            }
        } else if (g == 2) {
            compute_phase(base, macc);
            compute_phase(base + 2u * TILE16K, macc);
            if (s == 11) {       // fold m2: y0 += m2, y1 -= m2
#pragma unroll
                for (int mt = 0; mt < 4; mt++)
#pragma unroll
                    for (int nt = 0; nt < 4; nt++)
#pragma unroll
                        for (int e = 0; e < 4; e++) {
                            y0[mt][nt][e] += macc[mt][nt][e];
                            y1[mt][nt][e] -= macc[mt][nt][e];
                        }
            }
        } else {                 // g3: U3 negated, accumulates -m3 into y1
            compute_phase(base, y1);
            compute_phase(base + 2u * TILE16K, y1);
        }
    }

    // ---- epilogue: bias, channel max, fp16 k/v store ----
    const bool do_store = (m0 >= 512);
#pragma unroll
    for (int nt = 0; nt < 4; nt++) {
        const int ch = m0 + wc * 32 + nt * 8 + 2 * tg;
        const float b0 = bias_s[ch - m0], b1 = bias_s[ch - m0 + 1];
        float cm0 = -3.4e38f, cm1 = -3.4e38f;
#pragma unroll
        for (int mt = 0; mt < 4; mt++) {
            const int P = pair0 + wp * 64 + mt * 16 + gr;
            float v00 = y0[mt][nt][0] + b0, v01 = y0[mt][nt][1] + b1;   // Y[2P]
            float w00 = y1[mt][nt][0] + b0, w01 = y1[mt][nt][1] + b1;   // Y[2P+1]
            float v10 = y0[mt][nt][2] + b0, v11 = y0[mt][nt][3] + b1;   // Y[2(P+8)]
            float w10 = y1[mt][nt][2] + b0, w11 = y1[mt][nt][3] + b1;   // Y[2(P+8)+1]
            if (do_store) {
                __half* base = g_Yh + (size_t)(2 * P) * KVW + (ch - 512);
                *(__half2*)(base)                    = __floats2half2_rn(v00, v01);
                *(__half2*)(base + KVW)              = __floats2half2_rn(w00, w01);
                *(__half2*)(base + (size_t)16 * KVW) = __floats2half2_rn(v10, v11);
                *(__half2*)(base + (size_t)17 * KVW) = __floats2half2_rn(w10, w11);
            }
            cm0 = fmaxf(cm0, fmaxf(fmaxf(v00, w00), fmaxf(v10, w10)));
            cm1 = fmaxf(cm1, fmaxf(fmaxf(v01, w01), fmaxf(v11, w11)));
        }
#pragma unroll
        for (int o = 4; o <= 16; o <<= 1) {
            cm0 = fmaxf(cm0, __shfl_xor_sync(0xffffffffu, cm0, o));
            cm1 = fmaxf(cm1, __shfl_xor_sync(0xffffffffu, cm1, o));
        }
        if (lane < 4) {
            atomicMaxF(&g_cmax[b * MCH + ch], cm0);
            atomicMaxF(&g_cmax[b * MCH + ch + 1], cm1);
        }
    }
}

// ---------------------------------------------------------------------------
// attention stage 1: raw masked logits. grid = 32*8*8 (b, h, slice).
// ---------------------------------------------------------------------------
__global__ __launch_bounds__(256) void logits_kernel(const int* __restrict__ gmask,
                                                     const int* __restrict__ tmask) {
    __shared__ float q_s[64];
    const int bid   = blockIdx.x;
    const int slice = bid & 7;
    const int h     = (bid >> 3) & 7;
    const int b     = bid >> 6;
    const int tid   = threadIdx.x;
    const int lane  = tid & 31;
    const int w     = tid >> 5;

    if (tid < 64) q_s[tid] = g_cmax[b * MCH + h * HDd + tid];
    __syncthreads();

    const float scale = 0.04419417382415922f;   // 1/sqrt(512)
    const int j0  = slice * 256;
    const int cnt = (slice == NSL - 1) ? 257 : 256;
    const __half* Yk = g_Yh + (size_t)b * Ll * KVW + h * HDd;
    float* lg = g_lg + (b * Hh + h) * LGS;

    for (int jj = w; jj < cnt; jj += 8) {
        const int j = j0 + jj;
        float k0f, k1f;
        if (j == 0) {
            k0f = g_cmax[b * MCH + 512 + h * HDd + 2 * lane];
            k1f = g_cmax[b * MCH + 512 + h * HDd + 2 * lane + 1];
        } else {
            int l = j - 1;
            const __half2* r = (const __half2*)(Yk + (size_t)l * KVW) + lane;
            __half2 kv = r[0];
            if (l > 0)      kv = __hmax2(kv, r[-(KVW / 2)]);
            if (l < Ll - 1) kv = __hmax2(kv, r[KVW / 2]);
            float2 kf = __half22float2(kv);
            k0f = kf.x; k1f = kf.y;
        }
        float p = q_s[2 * lane] * k0f + q_s[2 * lane + 1] * k1f;
#pragma unroll
        for (int o = 16; o; o >>= 1) p += __shfl_down_sync(0xffffffffu, p, o);
        if (lane == 0) {
            int mk = (j == 0) ? gmask[b] : tmask[b * Ll + (j - 1)];
            lg[j] = mk ? p * scale : -1e30f;
        }
    }
}

// ---------------------------------------------------------------------------
// attention stage 2: softmax in place, probs scaled by 1/sum and g_mask.
// ---------------------------------------------------------------------------
__global__ __launch_bounds__(256) void softmax_kernel(const int* __restrict__ gmask) {
    __shared__ float red[256];
    const int b   = blockIdx.x >> 3;
    const int h   = blockIdx.x & 7;
    const int tid = threadIdx.x;
    float* lg = g_lg + (b * Hh + h) * LGS;

    float lm = -1e30f;
    for (int j = tid; j < LGS; j += 256) lm = fmaxf(lm, lg[j]);
    red[tid] = lm;
    __syncthreads();
    for (int s = 128; s; s >>= 1) {
        if (tid < s) red[tid] = fmaxf(red[tid], red[tid + s]);
        __syncthreads();
    }
    const float mx = red[0];
    __syncthreads();

    float ls = 0.f;
    float ev[9];
    int nv = 0;
    for (int j = tid; j < LGS; j += 256) {
        float e = expf(lg[j] - mx);
        ev[nv++] = e;
        ls += e;
    }
    red[tid] = ls;
    __syncthreads();
    for (int s = 128; s; s >>= 1) {
        if (tid < s) red[tid] += red[tid + s];
        __syncthreads();
    }
    const float fac = (1.0f / red[0]) * (float)gmask[b];
    nv = 0;
    for (int j = tid; j < LGS; j += 256) lg[j] = ev[nv++] * fac;
}

// ---------------------------------------------------------------------------
// attention stage 3: weighted V sum partials. grid = 32*8*8 (b, h, slice)
// ---------------------------------------------------------------------------
__global__ __launch_bounds__(256) void vsum_kernel() {
    __shared__ float red[256];
    const int bid   = blockIdx.x;
    const int slice = bid & 7;
    const int h     = (bid >> 3) & 7;
    const int b     = bid >> 6;
    const int tid   = threadIdx.x;
    const int d     = tid & 63;
    const int grp   = tid >> 6;

    const int j0  = slice * 256;
    const int cnt = (slice == NSL - 1) ? 257 : 256;
    const __half* Yv = g_Yh + (size_t)b * Ll * KVW + 512 + h * HDd + d;
    const float* lg = g_lg + (b * Hh + h) * LGS;

    float acc = 0.f;
    for (int jj = grp; jj < cnt; jj += 4) {
        const int j = j0 + jj;
        float v;
        if (j == 0) {
            v = g_cmax[b * MCH + 1024 + h * HDd + d];
        } else {
            int l = j - 1;
            const __half* r = Yv + (size_t)l * KVW;
            __half hv = r[0];
            if (l > 0)      hv = __hmax(hv, r[-KVW]);
            if (l < Ll - 1) hv = __hmax(hv, r[KVW]);
            v = __half2float(hv);
        }
        acc += lg[j] * v;
    }
    red[tid] = acc;
    __syncthreads();
    if (tid < 64) {
        float o = red[tid] + red[tid + 64] + red[tid + 128] + red[tid + 192];
        g_part[((b * Hh + h) * NSL + slice) * HDd + d] = o;
    }
}

// ---------------------------------------------------------------------------
// final: reduce slice partials, head-mix (Wh 8x8), output 1x1 conv (Wo).
// ---------------------------------------------------------------------------
__global__ __launch_bounds__(512) void final_kernel(const float* __restrict__ Wh,
                                                    const float* __restrict__ bh,
                                                    const float* __restrict__ Wo,
                                                    const float* __restrict__ bo,
                                                    float* __restrict__ out) {
    const int b    = blockIdx.x;
    const int quad = blockIdx.y;
    const int tid  = threadIdx.x;
    __shared__ float att_s[512];
    __shared__ float mid[512];

    {
        const int h = tid >> 6, d = tid & 63;
        const float* p = g_part + ((b * Hh + h) * NSL) * HDd + d;
        float s = 0.f;
#pragma unroll
        for (int sl = 0; sl < NSL; sl++) s += p[sl * HDd];
        att_s[tid] = s;
    }
    __syncthreads();

    {
        const int oh = tid >> 6, d = tid & 63;
        float s = bh[oh];
#pragma unroll
        for (int i = 0; i < 8; i++) s += Wh[oh * 8 + i] * att_s[i * HDd + d];
        mid[tid] = s;
    }
    __syncthreads();

    const int o    = quad * 128 + (tid >> 2);
    const int part = tid & 3;
    const float* wr = Wo + (size_t)o * 512 + part * 128;
    const float* mr = mid + part * 128;
    float s = 0.f;
#pragma unroll 16
    for (int i = 0; i < 128; i++) s += wr[i] * mr[i];
    s += __shfl_xor_sync(0xffffffffu, s, 1);
    s += __shfl_xor_sync(0xffffffffu, s, 2);
    if (part == 0) out[b * 512 + o] = s + bo[o];
}

// ---------------------------------------------------------------------------
// Launch
// ---------------------------------------------------------------------------
extern "C" void kernel_launch(void* const* d_in, const int* in_sizes, int n_in,
                              void* d_out, int out_size) {
    const float* t     = (const float*)d_in[0];
    const int*   gmask = (const int*)d_in[2];
    const int*   tmask = (const int*)d_in[3];
    const float* Wq    = (const float*)d_in[4];
    const float* bq    = (const float*)d_in[5];
    const float* Wk    = (const float*)d_in[6];
    const float* bk    = (const float*)d_in[7];
    const float* Wv    = (const float*)d_in[8];
    const float* bv    = (const float*)d_in[9];
    const float* Wh    = (const float*)d_in[10];
    const float* bh    = (const float*)d_in[11];
    const float* Wo    = (const float*)d_in[12];
    const float* bo    = (const float*)d_in[13];
    float* out = (float*)d_out;

    cudaFuncSetAttribute(conv_wino_kernel, cudaFuncAttributeMaxDynamicSharedMemorySize,
                         NSTAGEW * STAGEW);

    vtrans_kernel<<<(NPAIR * 128 + 255) / 256, 256>>>(t);
    wtrans_kernel<<<(MCH * 512 + 255) / 256, 256>>>(Wq, bq, Wk, bk, Wv, bv);
    conv_wino_kernel<<<dim3(MCH / TNW, NPAIR / PB), 256, NSTAGEW * STAGEW>>>();
    logits_kernel<<<Bb * Hh * NSL, 256>>>(gmask, tmask);
    softmax_kernel<<<Bb * Hh, 256>>>(gmask);
    vsum_kernel<<<Bb * Hh * NSL, 256>>>();
    final_kernel<<<dim3(Bb, 4), 512>>>(Wh, bh, Wo, bo, out);
}

// round 10
// speedup vs baseline: 1.6927x; 1.0377x over previous
#include <cuda_runtime.h>
#include <cuda_fp16.h>
#include <cstdint>
#include <cstddef>

// Problem constants
#define Bb 32
#define Ll 2048
#define Uu 512
#define Hh 8
#define HDd 64
#define NPOS (Bb * Ll)      // 65536
#define MCH 1536            // q|k|v channels (cmax indexing)
#define KVW 1024            // stored channels (k,v only), fp16
#define LGS 2049            // logits per (b,h)
#define NSL 8               // attention slices
#define NPAIR 32768         // Winograd output pairs (NPOS/2)

// Winograd GEMM config: M = pairs, N = channels, K = 512 per g, 4 g's
#define PB 128              // pairs per block tile
#define TNW 128             // channels per block tile
#define BKW 64
#define NSUPER 16           // superchunks (2 k-chunks each)
#define TILE16K 16384
#define STAGEW 65536        // [A0|B0|A1|B1]
#define NSTAGEW 3           // 192KB total

// ---------------------------------------------------------------------------
// Device scratch
// ---------------------------------------------------------------------------
__device__ __align__(16) __half g_V[4ull * NPAIR * 512];      // Winograd inputs, 128MB
__device__ __align__(16) __half g_U[4ull * MCH * 512];        // Winograd weights (U3 negated)
__device__ __align__(16) __half g_Yh[(size_t)NPOS * KVW];     // k|v conv out fp16, 128MB
__device__ float g_bias[MCH];
__device__ float g_cmax[Bb * MCH];
__device__ float g_lg[Bb * Hh * LGS];                         // logits -> probs
__device__ float g_part[Bb * Hh * NSL * HDd];                 // V partial sums

// ---------------------------------------------------------------------------
// Helpers
// ---------------------------------------------------------------------------
__device__ __forceinline__ void cp16(uint32_t dst, const void* src) {
    asm volatile("cp.async.cg.shared.global [%0], [%1], 16;\n"
                 :: "r"(dst), "l"(src));
}
#define CP_COMMIT() asm volatile("cp.async.commit_group;" ::: "memory")
#define CP_WAIT(n)  asm volatile("cp.async.wait_group %0;" :: "n"(n) : "memory")

__device__ __forceinline__ uint32_t su32(const void* p) {
    uint32_t a;
    asm("{ .reg .u64 t; cvta.to.shared.u64 t, %1; cvt.u32.u64 %0, t; }" : "=r"(a) : "l"(p));
    return a;
}

__device__ __forceinline__ void mma_f16(float c[4],
                                        uint32_t a0, uint32_t a1, uint32_t a2, uint32_t a3,
                                        uint32_t b0, uint32_t b1) {
    asm volatile(
        "mma.sync.aligned.m16n8k16.row.col.f32.f16.f16.f32 "
        "{%0,%1,%2,%3}, {%4,%5,%6,%7}, {%8,%9}, {%0,%1,%2,%3};\n"
        : "+f"(c[0]), "+f"(c[1]), "+f"(c[2]), "+f"(c[3])
        : "r"(a0), "r"(a1), "r"(a2), "r"(a3), "r"(b0), "r"(b1));
}

#define LDSM_X4(r0, r1, r2, r3, addr)                                         \
    asm volatile("ldmatrix.sync.aligned.m8n8.x4.shared.b16 {%0,%1,%2,%3}, [%4];" \
                 : "=r"(r0), "=r"(r1), "=r"(r2), "=r"(r3) : "r"(addr))

__device__ __forceinline__ void atomicMaxF(float* a, float v) {
    if (v >= 0.f) atomicMax((int*)a, __float_as_int(v));
    else          atomicMin((unsigned*)a, __float_as_uint(v));
}

// ---------------------------------------------------------------------------
// Winograd input transform: t(float) -> 4 fp16 arrays V_g[pair][512]
// ---------------------------------------------------------------------------
__global__ __launch_bounds__(256) void vtrans_kernel(const float* __restrict__ t) {
    int gid = blockIdx.x * 256 + threadIdx.x;        // NPAIR * 128
    if (gid >= NPAIR * 128) return;
    const int pair = gid >> 7;
    const int cg   = (gid & 127) << 2;
    const int lp   = pair & 1023;
    const float* base = t + ((size_t)pair * 2) * Uu + cg;   // x[2p] row (global)

    float4 w1 = *(const float4*)(base);
    float4 w2 = *(const float4*)(base + Uu);
    float4 w0 = make_float4(0.f, 0.f, 0.f, 0.f);
    float4 w3 = make_float4(0.f, 0.f, 0.f, 0.f);
    if (lp > 0)    w0 = *(const float4*)(base - Uu);
    if (lp < 1023) w3 = *(const float4*)(base + 2 * Uu);

    const size_t eo = (size_t)pair * 512 + cg;
    auto st = [&](int g, float a, float b, float c, float d) {
        __half2 lo = __floats2half2_rn(a, b);
        __half2 hi = __floats2half2_rn(c, d);
        *(uint2*)(g_V + (size_t)g * NPAIR * 512 + eo) =
            make_uint2(*(uint32_t*)&lo, *(uint32_t*)&hi);
    };
    st(0, w0.x - w2.x, w0.y - w2.y, w0.z - w2.z, w0.w - w2.w);
    st(1, w1.x + w2.x, w1.y + w2.y, w1.z + w2.z, w1.w + w2.w);
    st(2, w2.x - w1.x, w2.y - w1.y, w2.z - w1.z, w2.w - w1.w);
    st(3, w1.x - w3.x, w1.y - w3.y, w1.z - w3.z, w1.w - w3.w);
}

// ---------------------------------------------------------------------------
// Winograd weight transform (U3 stored NEGATED so g3 mma's directly into y1).
// Also: bias fill + cmax init (merged).
// ---------------------------------------------------------------------------
__global__ __launch_bounds__(256) void wtrans_kernel(
        const float* __restrict__ Wq, const float* __restrict__ bq,
        const float* __restrict__ Wk, const float* __restrict__ bk,
        const float* __restrict__ Wv, const float* __restrict__ bv) {
    int gid = blockIdx.x * 256 + threadIdx.x;
    if (gid < MCH)
        g_bias[gid] = gid < 512 ? bq[gid] : (gid < 1024 ? bk[gid - 512] : bv[gid - 1024]);
    if (gid < Bb * MCH) ((unsigned*)g_cmax)[gid] = 0xff800000u;   // -inf
    if (gid >= MCH * 512) return;
    const int mg = gid / 512;
    const int k  = gid % 512;
    const int conv = mg / 512;
    const int m    = mg % 512;
    const float* W = (conv == 0) ? Wq : ((conv == 1) ? Wk : Wv);
    const float g0 = W[m * 1536 + k * 3 + 0];
    const float g1 = W[m * 1536 + k * 3 + 1];
    const float g2 = W[m * 1536 + k * 3 + 2];
    const size_t eo = (size_t)mg * 512 + k;
    g_U[0ull * MCH * 512 + eo] = __float2half_rn(g0);
    g_U[1ull * MCH * 512 + eo] = __float2half_rn(0.5f * (g0 + g1 + g2));
    g_U[2ull * MCH * 512 + eo] = __float2half_rn(0.5f * (g0 - g1 + g2));
    g_U[3ull * MCH * 512 + eo] = __float2half_rn(-g2);           // NEGATED
}

// ---------------------------------------------------------------------------
// Winograd conv GEMM (unchanged from round 9 banked best)
// ---------------------------------------------------------------------------
__global__ __launch_bounds__(256, 1) void conv_wino_kernel() {
    extern __shared__ __align__(128) char dsmem[];   // 3 * 64KB
    __shared__ float bias_s[TNW];

    const int tid  = threadIdx.x;
    const int wid  = tid >> 5;
    const int lane = tid & 31;
    const int gr   = lane >> 2;
    const int tg   = lane & 3;
    const int wp   = wid & 1;           // 2 warps over pairs (64 each)
    const int wc   = wid >> 1;          // 4 warps over channels (32 each)
    const int m0    = blockIdx.x * TNW;
    const int pair0 = blockIdx.y * PB;
    const int b     = pair0 >> 10;

    if (tid < TNW) bias_s[tid] = g_bias[m0 + tid];

    const uint32_t smem0 = su32(dsmem);

    auto load_chunk = [&](int c, uint32_t cbase) {
        const int g  = c >> 3;
        const int k0 = (c & 7) * BKW;
#pragma unroll
        for (int p = 0; p < 4; p++) {           // A: 128 rows x 8 chunks
            int idx = p * 256 + tid;
            int row = idx >> 3;
            int j   = idx & 7;
            const void* src = g_V + (size_t)g * NPAIR * 512
                              + (size_t)(pair0 + row) * 512 + k0 + j * 8;
            cp16(cbase + (uint32_t)(row * 128 + ((j ^ (row & 7)) << 4)), src);
        }
#pragma unroll
        for (int p = 0; p < 4; p++) {           // B: 128 rows x 8 chunks
            int idx = p * 256 + tid;
            int row = idx >> 3;
            int j   = idx & 7;
            const void* src = g_U + (size_t)g * MCH * 512
                              + (size_t)(m0 + row) * 512 + k0 + j * 8;
            cp16(cbase + TILE16K + (uint32_t)(row * 128 + ((j ^ (row & 7)) << 4)), src);
        }
    };
    auto load_super = [&](int s, int slot) {
        const uint32_t base = smem0 + (uint32_t)slot * STAGEW;
        load_chunk(2 * s,     base);
        load_chunk(2 * s + 1, base + 2u * TILE16K);
    };

    const int sub = lane >> 3;          // 0..3
    const int lr  = lane & 7;
    uint32_t aRowOff[4], bRowOff[2];
#pragma unroll
    for (int mt = 0; mt < 4; mt++)
        aRowOff[mt] = (uint32_t)((wp * 64 + mt * 16 + ((sub & 1) << 3) + lr) * 128);
#pragma unroll
    for (int p = 0; p < 2; p++)
        bRowOff[p] = (uint32_t)((wc * 32 + p * 16 + ((sub >> 1) << 3) + lr) * 128);
    const int aSub = sub >> 1;
    const int bSub = sub & 1;

    float y0[4][4][4], y1[4][4][4], macc[4][4][4];
#pragma unroll
    for (int i = 0; i < 4; i++)
#pragma unroll
        for (int j = 0; j < 4; j++)
#pragma unroll
            for (int e = 0; e < 4; e++) { y0[i][j][e] = 0.f; y1[i][j][e] = 0.f; macc[i][j][e] = 0.f; }

    auto compute_phase = [&](uint32_t abase, float (&acc)[4][4][4]) {
        const uint32_t bbase = abase + TILE16K;
#pragma unroll
        for (int kk = 0; kk < 4; kk++) {
            const uint32_t aCh = (uint32_t)(((2 * kk + aSub) ^ lr) << 4);
            const uint32_t bCh = (uint32_t)(((2 * kk + bSub) ^ lr) << 4);
            uint32_t a[4][4];
#pragma unroll
            for (int mt = 0; mt < 4; mt++)
                LDSM_X4(a[mt][0], a[mt][1], a[mt][2], a[mt][3],
                        abase + aRowOff[mt] + aCh);
            uint32_t bf[4][2];
#pragma unroll
            for (int p = 0; p < 2; p++)
                LDSM_X4(bf[2 * p][0], bf[2 * p][1], bf[2 * p + 1][0], bf[2 * p + 1][1],
                        bbase + bRowOff[p] + bCh);
#pragma unroll
            for (int mt = 0; mt < 4; mt++)
#pragma unroll
                for (int nt = 0; nt < 4; nt++)
                    mma_f16(acc[mt][nt], a[mt][0], a[mt][1], a[mt][2], a[mt][3],
                            bf[nt][0], bf[nt][1]);
        }
    };

    load_super(0, 0); CP_COMMIT();
    load_super(1, 1); CP_COMMIT();

    for (int s = 0; s < NSUPER; s++) {
        if (s + 1 < NSUPER) { CP_WAIT(1); } else { CP_WAIT(0); }
        __syncthreads();
        if (s + 2 < NSUPER) { load_super(s + 2, (s + 2) % NSTAGEW); CP_COMMIT(); }

        const uint32_t base = smem0 + (uint32_t)(s % NSTAGEW) * STAGEW;
        const int g = s >> 2;
        if (g == 0) {
            compute_phase(base, y0);
            compute_phase(base + 2u * TILE16K, y0);
        } else if (g == 1) {
            compute_phase(base, macc);
            compute_phase(base + 2u * TILE16K, macc);
            if (s == 7) {
#pragma unroll
                for (int mt = 0; mt < 4; mt++)
#pragma unroll
                    for (int nt = 0; nt < 4; nt++)
#pragma unroll
                        for (int e = 0; e < 4; e++) {
                            y0[mt][nt][e] += macc[mt][nt][e];
                            y1[mt][nt][e] += macc[mt][nt][e];
                            macc[mt][nt][e] = 0.f;
                        }
            }
        } else if (g == 2) {
            compute_phase(base, macc);
            compute_phase(base + 2u * TILE16K, macc);
            if (s == 11) {
#pragma unroll
                for (int mt = 0; mt < 4; mt++)
#pragma unroll
                    for (int nt = 0; nt < 4; nt++)
#pragma unroll
                        for (int e = 0; e < 4; e++) {
                            y0[mt][nt][e] += macc[mt][nt][e];
                            y1[mt][nt][e] -= macc[mt][nt][e];
                        }
            }
        } else {
            compute_phase(base, y1);
            compute_phase(base + 2u * TILE16K, y1);
        }
    }

    const bool do_store = (m0 >= 512);
#pragma unroll
    for (int nt = 0; nt < 4; nt++) {
        const int ch = m0 + wc * 32 + nt * 8 + 2 * tg;
        const float b0 = bias_s[ch - m0], b1 = bias_s[ch - m0 + 1];
        float cm0 = -3.4e38f, cm1 = -3.4e38f;
#pragma unroll
        for (int mt = 0; mt < 4; mt++) {
            const int P = pair0 + wp * 64 + mt * 16 + gr;
            float v00 = y0[mt][nt][0] + b0, v01 = y0[mt][nt][1] + b1;
            float w00 = y1[mt][nt][0] + b0, w01 = y1[mt][nt][1] + b1;
            float v10 = y0[mt][nt][2] + b0, v11 = y0[mt][nt][3] + b1;
            float w10 = y1[mt][nt][2] + b0, w11 = y1[mt][nt][3] + b1;
            if (do_store) {
                __half* base = g_Yh + (size_t)(2 * P) * KVW + (ch - 512);
                *(__half2*)(base)                    = __floats2half2_rn(v00, v01);
                *(__half2*)(base + KVW)              = __floats2half2_rn(w00, w01);
                *(__half2*)(base + (size_t)16 * KVW) = __floats2half2_rn(v10, v11);
                *(__half2*)(base + (size_t)17 * KVW) = __floats2half2_rn(w10, w11);
            }
            cm0 = fmaxf(cm0, fmaxf(fmaxf(v00, w00), fmaxf(v10, w10)));
            cm1 = fmaxf(cm1, fmaxf(fmaxf(v01, w01), fmaxf(v11, w11)));
        }
#pragma unroll
        for (int o = 4; o <= 16; o <<= 1) {
            cm0 = fmaxf(cm0, __shfl_xor_sync(0xffffffffu, cm0, o));
            cm1 = fmaxf(cm1, __shfl_xor_sync(0xffffffffu, cm1, o));
        }
        if (lane < 4) {
            atomicMaxF(&g_cmax[b * MCH + ch], cm0);
            atomicMaxF(&g_cmax[b * MCH + ch + 1], cm1);
        }
    }
}

// ---------------------------------------------------------------------------
// attention stage 1: raw masked logits. grid = 32*8*8 (b, h, slice).
// Key 0 (global max key) handled by slice 0 / warp 0; slices cover local
// rows l in [slice*256, slice*256+256), logit index j = l + 1.
// 2-key unroll per warp iteration for MLP + shfl-chain overlap.
// ---------------------------------------------------------------------------
__global__ __launch_bounds__(256) void logits_kernel(const int* __restrict__ gmask,
                                                     const int* __restrict__ tmask) {
    __shared__ float q_s[64];
    __shared__ int   mk_s[256];
    const int bid   = blockIdx.x;
    const int slice = bid & 7;
    const int h     = (bid >> 3) & 7;
    const int b     = bid >> 6;
    const int tid   = threadIdx.x;
    const int lane  = tid & 31;
    const int w     = tid >> 5;
    const int l0    = slice * 256;

    if (tid < 64) q_s[tid] = g_cmax[b * MCH + h * HDd + tid];
    mk_s[tid] = tmask[b * Ll + l0 + tid];
    __syncthreads();

    const float scale = 0.04419417382415922f;   // 1/sqrt(512)
    float* lg = g_lg + (b * Hh + h) * LGS;
    const float qa = q_s[2 * lane], qb = q_s[2 * lane + 1];
    const __half2* Y2 = (const __half2*)(g_Yh + (size_t)b * Ll * KVW + h * HDd) + lane;

    if (slice == 0 && w == 0) {   // key 0: global max key
        float k0f = g_cmax[b * MCH + 512 + h * HDd + 2 * lane];
        float k1f = g_cmax[b * MCH + 512 + h * HDd + 2 * lane + 1];
        float p = qa * k0f + qb * k1f;
#pragma unroll
        for (int o = 16; o; o >>= 1) p += __shfl_down_sync(0xffffffffu, p, o);
        if (lane == 0) lg[0] = gmask[b] ? p * scale : -1e30f;
    }

    for (int ii = w; ii < 256; ii += 16) {
        const int la = l0 + ii;
        const int lb = la + 8;
        const __half2* ra = Y2 + (size_t)la * (KVW / 2);
        const __half2* rb = Y2 + (size_t)lb * (KVW / 2);
        __half2 ka = ra[0];
        __half2 kb = rb[0];
        __half2 kap = ra[KVW / 2];                  // la <= 2039 < 2047 always
        __half2 kbm = rb[-(KVW / 2)];               // lb >= 8 > 0 always
        if (la > 0)       ka = __hmax2(ka, ra[-(KVW / 2)]);
        ka = __hmax2(ka, kap);
        kb = __hmax2(kb, kbm);
        if (lb < Ll - 1)  kb = __hmax2(kb, rb[KVW / 2]);
        float2 fa = __half22float2(ka);
        float2 fb = __half22float2(kb);
        float pa = qa * fa.x + qb * fa.y;
        float pb = qa * fb.x + qb * fb.y;
#pragma unroll
        for (int o = 16; o; o >>= 1) {
            pa += __shfl_down_sync(0xffffffffu, pa, o);
            pb += __shfl_down_sync(0xffffffffu, pb, o);
        }
        if (lane == 0) {
            lg[la + 1] = mk_s[ii]     ? pa * scale : -1e30f;
            lg[lb + 1] = mk_s[ii + 8] ? pb * scale : -1e30f;
        }
    }
}

// ---------------------------------------------------------------------------
// attention stage 2: softmax in place, probs scaled by 1/sum and g_mask.
// ---------------------------------------------------------------------------
__global__ __launch_bounds__(256) void softmax_kernel(const int* __restrict__ gmask) {
    __shared__ float red[256];
    const int b   = blockIdx.x >> 3;
    const int h   = blockIdx.x & 7;
    const int tid = threadIdx.x;
    float* lg = g_lg + (b * Hh + h) * LGS;

    float lm = -1e30f;
    for (int j = tid; j < LGS; j += 256) lm = fmaxf(lm, lg[j]);
    red[tid] = lm;
    __syncthreads();
    for (int s = 128; s; s >>= 1) {
        if (tid < s) red[tid] = fmaxf(red[tid], red[tid + s]);
        __syncthreads();
    }
    const float mx = red[0];
    __syncthreads();

    float ls = 0.f;
    float ev[9];
    int nv = 0;
    for (int j = tid; j < LGS; j += 256) {
        float e = expf(lg[j] - mx);
        ev[nv++] = e;
        ls += e;
    }
    red[tid] = ls;
    __syncthreads();
    for (int s = 128; s; s >>= 1) {
        if (tid < s) red[tid] += red[tid + s];
        __syncthreads();
    }
    const float fac = (1.0f / red[0]) * (float)gmask[b];
    nv = 0;
    for (int j = tid; j < LGS; j += 256) lg[j] = ev[nv++] * fac;
}

// ---------------------------------------------------------------------------
// attention stage 3: weighted V sum partials. grid = 32*8*8 (b, h, slice).
// Key 0 peeled to slice 0 / grp 0; 2-key unroll.
// ---------------------------------------------------------------------------
__global__ __launch_bounds__(256) void vsum_kernel() {
    __shared__ float red[256];
    const int bid   = blockIdx.x;
    const int slice = bid & 7;
    const int h     = (bid >> 3) & 7;
    const int b     = bid >> 6;
    const int tid   = threadIdx.x;
    const int d     = tid & 63;
    const int grp   = tid >> 6;
    const int l0    = slice * 256;

    const __half* Yv = g_Yh + (size_t)b * Ll * KVW + 512 + h * HDd + d;
    const float* lg = g_lg + (b * Hh + h) * LGS;

    float acc = 0.f;
    if (slice == 0 && grp == 0)
        acc = lg[0] * g_cmax[b * MCH + 1024 + h * HDd + d];

    for (int ii = grp; ii < 256; ii += 8) {
        const int la = l0 + ii;
        const int lb = la + 4;
        const __half* ra = Yv + (size_t)la * KVW;
        const __half* rb = Yv + (size_t)lb * KVW;
        __half va = ra[0];
        __half vb = rb[0];
        __half vap = ra[KVW];                  // la <= 2043 < 2047 always
        __half vbm = rb[-KVW];                 // lb >= 4 > 0 always
        if (la > 0)      va = __hmax(va, ra[-KVW]);
        va = __hmax(va, vap);
        vb = __hmax(vb, vbm);
        if (lb < Ll - 1) vb = __hmax(vb, rb[KVW]);
        acc += lg[la + 1] * __half2float(va) + lg[lb + 1] * __half2float(vb);
    }
    red[tid] = acc;
    __syncthreads();
    if (tid < 64) {
        float o = red[tid] + red[tid + 64] + red[tid + 128] + red[tid + 192];
        g_part[((b * Hh + h) * NSL + slice) * HDd + d] = o;
    }
}

// ---------------------------------------------------------------------------
// final: reduce slice partials, head-mix (Wh 8x8), output 1x1 conv (Wo).
// ---------------------------------------------------------------------------
__global__ __launch_bounds__(512) void final_kernel(const float* __restrict__ Wh,
                                                    const float* __restrict__ bh,
                                                    const float* __restrict__ Wo,
                                                    const float* __restrict__ bo,
                                                    float* __restrict__ out) {
    const int b    = blockIdx.x;
    const int quad = blockIdx.y;
    const int tid  = threadIdx.x;
    __shared__ float att_s[512];
    __shared__ float mid[512];

    {
        const int h = tid >> 6, d = tid & 63;
        const float* p = g_part + ((b * Hh + h) * NSL) * HDd + d;
        float s = 0.f;
#pragma unroll
        for (int sl = 0; sl < NSL; sl++) s += p[sl * HDd];
        att_s[tid] = s;
    }
    __syncthreads();

    {
        const int oh = tid >> 6, d = tid & 63;
        float s = bh[oh];
#pragma unroll
        for (int i = 0; i < 8; i++) s += Wh[oh * 8 + i] * att_s[i * HDd + d];
        mid[tid] = s;
    }
    __syncthreads();

    const int o    = quad * 128 + (tid >> 2);
    const int part = tid & 3;
    const float* wr = Wo + (size_t)o * 512 + part * 128;
    const float* mr = mid + part * 128;
    float s = 0.f;
#pragma unroll 16
    for (int i = 0; i < 128; i++) s += wr[i] * mr[i];
    s += __shfl_xor_sync(0xffffffffu, s, 1);
    s += __shfl_xor_sync(0xffffffffu, s, 2);
    if (part == 0) out[b * 512 + o] = s + bo[o];
}

// ---------------------------------------------------------------------------
// Launch
// ---------------------------------------------------------------------------
extern "C" void kernel_launch(void* const* d_in, const int* in_sizes, int n_in,
                              void* d_out, int out_size) {
    const float* t     = (const float*)d_in[0];
    const int*   gmask = (const int*)d_in[2];
    const int*   tmask = (const int*)d_in[3];
    const float* Wq    = (const float*)d_in[4];
    const float* bq    = (const float*)d_in[5];
    const float* Wk    = (const float*)d_in[6];
    const float* bk    = (const float*)d_in[7];
    const float* Wv    = (const float*)d_in[8];
    const float* bv    = (const float*)d_in[9];
    const float* Wh    = (const float*)d_in[10];
    const float* bh    = (const float*)d_in[11];
    const float* Wo    = (const float*)d_in[12];
    const float* bo    = (const float*)d_in[13];
    float* out = (float*)d_out;

    cudaFuncSetAttribute(conv_wino_kernel, cudaFuncAttributeMaxDynamicSharedMemorySize,
                         NSTAGEW * STAGEW);

    vtrans_kernel<<<(NPAIR * 128 + 255) / 256, 256>>>(t);
    wtrans_kernel<<<(MCH * 512 + 255) / 256, 256>>>(Wq, bq, Wk, bk, Wv, bv);
    conv_wino_kernel<<<dim3(MCH / TNW, NPAIR / PB), 256, NSTAGEW * STAGEW>>>();
    logits_kernel<<<Bb * Hh * NSL, 256>>>(gmask, tmask);
    softmax_kernel<<<Bb * Hh, 256>>>(gmask);
    vsum_kernel<<<Bb * Hh * NSL, 256>>>();
    final_kernel<<<dim3(Bb, 4), 512>>>(Wh, bh, Wo, bo, out);
}

// round 11
// speedup vs baseline: 1.7542x; 1.0363x over previous
#include <cuda_runtime.h>
#include <cuda_fp16.h>
#include <cstdint>
#include <cstddef>

// Problem constants
#define Bb 32
#define Ll 2048
#define Uu 512
#define Hh 8
#define HDd 64
#define NPOS (Bb * Ll)      // 65536
#define MCH 1536            // q|k|v channels (cmax indexing)
#define KVW 1024            // stored channels (k,v only), fp16
#define LGS 2049            // logits per (b,h)
#define NSL 8               // attention slices
#define NPAIR 32768         // Winograd output pairs (NPOS/2)

// Winograd GEMM config: M = pairs, N = channels, K = 512 per g, 4 g's
#define PB 128              // pairs per block tile
#define TNW 128             // channels per block tile
#define BKW 64
#define NSUPER 16           // superchunks (2 k-chunks each)
#define TILE16K 16384
#define STAGEW 65536        // [A0|B0|A1|B1]
#define NSTAGEW 3           // 192KB total

// ---------------------------------------------------------------------------
// Device scratch
// ---------------------------------------------------------------------------
__device__ __align__(16) __half g_V[4ull * NPAIR * 512];      // Winograd inputs, 128MB
__device__ __align__(16) __half g_U[4ull * MCH * 512];        // Winograd weights (U3 negated)
__device__ __align__(16) __half g_Yh[(size_t)NPOS * KVW];     // k|v conv out fp16, 128MB
__device__ float g_bias[MCH];
__device__ float g_cmax[Bb * MCH];
__device__ float g_lg[Bb * Hh * LGS];                         // logits -> probs
__device__ float g_part[Bb * Hh * NSL * HDd];                 // V partial sums

// ---------------------------------------------------------------------------
// Helpers
// ---------------------------------------------------------------------------
__device__ __forceinline__ void cp16(uint32_t dst, const void* src) {
    asm volatile("cp.async.cg.shared.global [%0], [%1], 16;\n"
                 :: "r"(dst), "l"(src));
}
#define CP_COMMIT() asm volatile("cp.async.commit_group;" ::: "memory")
#define CP_WAIT(n)  asm volatile("cp.async.wait_group %0;" :: "n"(n) : "memory")

__device__ __forceinline__ uint32_t su32(const void* p) {
    uint32_t a;
    asm("{ .reg .u64 t; cvta.to.shared.u64 t, %1; cvt.u32.u64 %0, t; }" : "=r"(a) : "l"(p));
    return a;
}

__device__ __forceinline__ void mma_f16(float c[4],
                                        uint32_t a0, uint32_t a1, uint32_t a2, uint32_t a3,
                                        uint32_t b0, uint32_t b1) {
    asm volatile(
        "mma.sync.aligned.m16n8k16.row.col.f32.f16.f16.f32 "
        "{%0,%1,%2,%3}, {%4,%5,%6,%7}, {%8,%9}, {%0,%1,%2,%3};\n"
        : "+f"(c[0]), "+f"(c[1]), "+f"(c[2]), "+f"(c[3])
        : "r"(a0), "r"(a1), "r"(a2), "r"(a3), "r"(b0), "r"(b1));
}

#define LDSM_X4(r0, r1, r2, r3, addr)                                         \
    asm volatile("ldmatrix.sync.aligned.m8n8.x4.shared.b16 {%0,%1,%2,%3}, [%4];" \
                 : "=r"(r0), "=r"(r1), "=r"(r2), "=r"(r3) : "r"(addr))

__device__ __forceinline__ void atomicMaxF(float* a, float v) {
    if (v >= 0.f) atomicMax((int*)a, __float_as_int(v));
    else          atomicMin((unsigned*)a, __float_as_uint(v));
}

// ---------------------------------------------------------------------------
// Winograd input transform: t(float) -> 4 fp16 arrays V_g[pair][512]
// ---------------------------------------------------------------------------
__global__ __launch_bounds__(256) void vtrans_kernel(const float* __restrict__ t) {
    int gid = blockIdx.x * 256 + threadIdx.x;        // NPAIR * 128
    if (gid >= NPAIR * 128) return;
    const int pair = gid >> 7;
    const int cg   = (gid & 127) << 2;
    const int lp   = pair & 1023;
    const float* base = t + ((size_t)pair * 2) * Uu + cg;   // x[2p] row (global)

    float4 w1 = *(const float4*)(base);
    float4 w2 = *(const float4*)(base + Uu);
    float4 w0 = make_float4(0.f, 0.f, 0.f, 0.f);
    float4 w3 = make_float4(0.f, 0.f, 0.f, 0.f);
    if (lp > 0)    w0 = *(const float4*)(base - Uu);
    if (lp < 1023) w3 = *(const float4*)(base + 2 * Uu);

    const size_t eo = (size_t)pair * 512 + cg;
    auto st = [&](int g, float a, float b, float c, float d) {
        __half2 lo = __floats2half2_rn(a, b);
        __half2 hi = __floats2half2_rn(c, d);
        *(uint2*)(g_V + (size_t)g * NPAIR * 512 + eo) =
            make_uint2(*(uint32_t*)&lo, *(uint32_t*)&hi);
    };
    st(0, w0.x - w2.x, w0.y - w2.y, w0.z - w2.z, w0.w - w2.w);
    st(1, w1.x + w2.x, w1.y + w2.y, w1.z + w2.z, w1.w + w2.w);
    st(2, w2.x - w1.x, w2.y - w1.y, w2.z - w1.z, w2.w - w1.w);
    st(3, w1.x - w3.x, w1.y - w3.y, w1.z - w3.z, w1.w - w3.w);
}

// ---------------------------------------------------------------------------
// Winograd weight transform (U3 stored NEGATED so g3 mma's directly into y1).
// Also: bias fill + cmax init (merged).
// ---------------------------------------------------------------------------
__global__ __launch_bounds__(256) void wtrans_kernel(
        const float* __restrict__ Wq, const float* __restrict__ bq,
        const float* __restrict__ Wk, const float* __restrict__ bk,
        const float* __restrict__ Wv, const float* __restrict__ bv) {
    int gid = blockIdx.x * 256 + threadIdx.x;
    if (gid < MCH)
        g_bias[gid] = gid < 512 ? bq[gid] : (gid < 1024 ? bk[gid - 512] : bv[gid - 1024]);
    if (gid < Bb * MCH) ((unsigned*)g_cmax)[gid] = 0xff800000u;   // -inf
    if (gid >= MCH * 512) return;
    const int mg = gid / 512;
    const int k  = gid % 512;
    const int conv = mg / 512;
    const int m    = mg % 512;
    const float* W = (conv == 0) ? Wq : ((conv == 1) ? Wk : Wv);
    const float g0 = W[m * 1536 + k * 3 + 0];
    const float g1 = W[m * 1536 + k * 3 + 1];
    const float g2 = W[m * 1536 + k * 3 + 2];
    const size_t eo = (size_t)mg * 512 + k;
    g_U[0ull * MCH * 512 + eo] = __float2half_rn(g0);
    g_U[1ull * MCH * 512 + eo] = __float2half_rn(0.5f * (g0 + g1 + g2));
    g_U[2ull * MCH * 512 + eo] = __float2half_rn(0.5f * (g0 - g1 + g2));
    g_U[3ull * MCH * 512 + eo] = __float2half_rn(-g2);           // NEGATED
}

// ---------------------------------------------------------------------------
// Winograd conv GEMM (unchanged from round 9/10 banked best)
// ---------------------------------------------------------------------------
__global__ __launch_bounds__(256, 1) void conv_wino_kernel() {
    extern __shared__ __align__(128) char dsmem[];   // 3 * 64KB
    __shared__ float bias_s[TNW];

    const int tid  = threadIdx.x;
    const int wid  = tid >> 5;
    const int lane = tid & 31;
    const int gr   = lane >> 2;
    const int tg   = lane & 3;
    const int wp   = wid & 1;           // 2 warps over pairs (64 each)
    const int wc   = wid >> 1;          // 4 warps over channels (32 each)
    const int m0    = blockIdx.x * TNW;
    const int pair0 = blockIdx.y * PB;
    const int b     = pair0 >> 10;

    if (tid < TNW) bias_s[tid] = g_bias[m0 + tid];

    const uint32_t smem0 = su32(dsmem);

    auto load_chunk = [&](int c, uint32_t cbase) {
        const int g  = c >> 3;
        const int k0 = (c & 7) * BKW;
#pragma unroll
        for (int p = 0; p < 4; p++) {           // A: 128 rows x 8 chunks
            int idx = p * 256 + tid;
            int row = idx >> 3;
            int j   = idx & 7;
            const void* src = g_V + (size_t)g * NPAIR * 512
                              + (size_t)(pair0 + row) * 512 + k0 + j * 8;
            cp16(cbase + (uint32_t)(row * 128 + ((j ^ (row & 7)) << 4)), src);
        }
#pragma unroll
        for (int p = 0; p < 4; p++) {           // B: 128 rows x 8 chunks
            int idx = p * 256 + tid;
            int row = idx >> 3;
            int j   = idx & 7;
            const void* src = g_U + (size_t)g * MCH * 512
                              + (size_t)(m0 + row) * 512 + k0 + j * 8;
            cp16(cbase + TILE16K + (uint32_t)(row * 128 + ((j ^ (row & 7)) << 4)), src);
        }
    };
    auto load_super = [&](int s, int slot) {
        const uint32_t base = smem0 + (uint32_t)slot * STAGEW;
        load_chunk(2 * s,     base);
        load_chunk(2 * s + 1, base + 2u * TILE16K);
    };

    const int sub = lane >> 3;          // 0..3
    const int lr  = lane & 7;
    uint32_t aRowOff[4], bRowOff[2];
#pragma unroll
    for (int mt = 0; mt < 4; mt++)
        aRowOff[mt] = (uint32_t)((wp * 64 + mt * 16 + ((sub & 1) << 3) + lr) * 128);
#pragma unroll
    for (int p = 0; p < 2; p++)
        bRowOff[p] = (uint32_t)((wc * 32 + p * 16 + ((sub >> 1) << 3) + lr) * 128);
    const int aSub = sub >> 1;
    const int bSub = sub & 1;

    float y0[4][4][4], y1[4][4][4], macc[4][4][4];
#pragma unroll
    for (int i = 0; i < 4; i++)
#pragma unroll
        for (int j = 0; j < 4; j++)
#pragma unroll
            for (int e = 0; e < 4; e++) { y0[i][j][e] = 0.f; y1[i][j][e] = 0.f; macc[i][j][e] = 0.f; }

    auto compute_phase = [&](uint32_t abase, float (&acc)[4][4][4]) {
        const uint32_t bbase = abase + TILE16K;
#pragma unroll
        for (int kk = 0; kk < 4; kk++) {
            const uint32_t aCh = (uint32_t)(((2 * kk + aSub) ^ lr) << 4);
            const uint32_t bCh = (uint32_t)(((2 * kk + bSub) ^ lr) << 4);
            uint32_t a[4][4];
#pragma unroll
            for (int mt = 0; mt < 4; mt++)
                LDSM_X4(a[mt][0], a[mt][1], a[mt][2], a[mt][3],
                        abase + aRowOff[mt] + aCh);
            uint32_t bf[4][2];
#pragma unroll
            for (int p = 0; p < 2; p++)
                LDSM_X4(bf[2 * p][0], bf[2 * p][1], bf[2 * p + 1][0], bf[2 * p + 1][1],
                        bbase + bRowOff[p] + bCh);
#pragma unroll
            for (int mt = 0; mt < 4; mt++)
#pragma unroll
                for (int nt = 0; nt < 4; nt++)
                    mma_f16(acc[mt][nt], a[mt][0], a[mt][1], a[mt][2], a[mt][3],
                            bf[nt][0], bf[nt][1]);
        }
    };

    load_super(0, 0); CP_COMMIT();
    load_super(1, 1); CP_COMMIT();

    for (int s = 0; s < NSUPER; s++) {
        if (s + 1 < NSUPER) { CP_WAIT(1); } else { CP_WAIT(0); }
        __syncthreads();
        if (s + 2 < NSUPER) { load_super(s + 2, (s + 2) % NSTAGEW); CP_COMMIT(); }

        const uint32_t base = smem0 + (uint32_t)(s % NSTAGEW) * STAGEW;
        const int g = s >> 2;
        if (g == 0) {
            compute_phase(base, y0);
            compute_phase(base + 2u * TILE16K, y0);
        } else if (g == 1) {
            compute_phase(base, macc);
            compute_phase(base + 2u * TILE16K, macc);
            if (s == 7) {
#pragma unroll
                for (int mt = 0; mt < 4; mt++)
#pragma unroll
                    for (int nt = 0; nt < 4; nt++)
#pragma unroll
                        for (int e = 0; e < 4; e++) {
                            y0[mt][nt][e] += macc[mt][nt][e];
                            y1[mt][nt][e] += macc[mt][nt][e];
                            macc[mt][nt][e] = 0.f;
                        }
            }
        } else if (g == 2) {
            compute_phase(base, macc);
            compute_phase(base + 2u * TILE16K, macc);
            if (s == 11) {
#pragma unroll
                for (int mt = 0; mt < 4; mt++)
#pragma unroll
                    for (int nt = 0; nt < 4; nt++)
#pragma unroll
                        for (int e = 0; e < 4; e++) {
                            y0[mt][nt][e] += macc[mt][nt][e];
                            y1[mt][nt][e] -= macc[mt][nt][e];
                        }
            }
        } else {
            compute_phase(base, y1);
            compute_phase(base + 2u * TILE16K, y1);
        }
    }

    const bool do_store = (m0 >= 512);
#pragma unroll
    for (int nt = 0; nt < 4; nt++) {
        const int ch = m0 + wc * 32 + nt * 8 + 2 * tg;
        const float b0 = bias_s[ch - m0], b1 = bias_s[ch - m0 + 1];
        float cm0 = -3.4e38f, cm1 = -3.4e38f;
#pragma unroll
        for (int mt = 0; mt < 4; mt++) {
            const int P = pair0 + wp * 64 + mt * 16 + gr;
            float v00 = y0[mt][nt][0] + b0, v01 = y0[mt][nt][1] + b1;
            float w00 = y1[mt][nt][0] + b0, w01 = y1[mt][nt][1] + b1;
            float v10 = y0[mt][nt][2] + b0, v11 = y0[mt][nt][3] + b1;
            float w10 = y1[mt][nt][2] + b0, w11 = y1[mt][nt][3] + b1;
            if (do_store) {
                __half* base = g_Yh + (size_t)(2 * P) * KVW + (ch - 512);
                *(__half2*)(base)                    = __floats2half2_rn(v00, v01);
                *(__half2*)(base + KVW)              = __floats2half2_rn(w00, w01);
                *(__half2*)(base + (size_t)16 * KVW) = __floats2half2_rn(v10, v11);
                *(__half2*)(base + (size_t)17 * KVW) = __floats2half2_rn(w10, w11);
            }
            cm0 = fmaxf(cm0, fmaxf(fmaxf(v00, w00), fmaxf(v10, w10)));
            cm1 = fmaxf(cm1, fmaxf(fmaxf(v01, w01), fmaxf(v11, w11)));
        }
#pragma unroll
        for (int o = 4; o <= 16; o <<= 1) {
            cm0 = fmaxf(cm0, __shfl_xor_sync(0xffffffffu, cm0, o));
            cm1 = fmaxf(cm1, __shfl_xor_sync(0xffffffffu, cm1, o));
        }
        if (lane < 4) {
            atomicMaxF(&g_cmax[b * MCH + ch], cm0);
            atomicMaxF(&g_cmax[b * MCH + ch + 1], cm1);
        }
    }
}

// ---------------------------------------------------------------------------
// attention stage 1: raw masked logits. grid = 32*8*8 (b, h, slice).
// Key 0 handled by slice 0 / warp 0. Each warp covers 16 keys of its slice,
// 4-key unroll (MLP 12, four interleaved shfl chains).
// ---------------------------------------------------------------------------
__global__ __launch_bounds__(256) void logits_kernel(const int* __restrict__ gmask,
                                                     const int* __restrict__ tmask) {
    __shared__ float q_s[64];
    __shared__ int   mk_s[256];
    const int bid   = blockIdx.x;
    const int slice = bid & 7;
    const int h     = (bid >> 3) & 7;
    const int b     = bid >> 6;
    const int tid   = threadIdx.x;
    const int lane  = tid & 31;
    const int w     = tid >> 5;
    const int l0    = slice * 256;

    if (tid < 64) q_s[tid] = g_cmax[b * MCH + h * HDd + tid];
    mk_s[tid] = tmask[b * Ll + l0 + tid];
    __syncthreads();

    const float scale = 0.04419417382415922f;   // 1/sqrt(512)
    float* lg = g_lg + (b * Hh + h) * LGS;
    const float qa = q_s[2 * lane], qb = q_s[2 * lane + 1];
    const __half2* Y2 = (const __half2*)(g_Yh + (size_t)b * Ll * KVW + h * HDd) + lane;

    if (slice == 0 && w == 0) {   // key 0: global max key
        float k0f = g_cmax[b * MCH + 512 + h * HDd + 2 * lane];
        float k1f = g_cmax[b * MCH + 512 + h * HDd + 2 * lane + 1];
        float p = qa * k0f + qb * k1f;
#pragma unroll
        for (int o = 16; o; o >>= 1) p += __shfl_down_sync(0xffffffffu, p, o);
        if (lane == 0) lg[0] = gmask[b] ? p * scale : -1e30f;
    }

#pragma unroll
    for (int it = 0; it < 4; it++) {
        const int i0 = w + 64 * it;          // keys i0, i0+16, i0+32, i0+48
        float p[4];
#pragma unroll
        for (int u = 0; u < 4; u++) {
            const int l = l0 + i0 + 16 * u;
            const __half2* r = Y2 + (size_t)l * (KVW / 2);
            __half2 kv = r[0];
            if (l > 0)      kv = __hmax2(kv, r[-(KVW / 2)]);
            if (l < Ll - 1) kv = __hmax2(kv, r[KVW / 2]);
            float2 f = __half22float2(kv);
            p[u] = qa * f.x + qb * f.y;
        }
#pragma unroll
        for (int o = 16; o; o >>= 1) {
            p[0] += __shfl_down_sync(0xffffffffu, p[0], o);
            p[1] += __shfl_down_sync(0xffffffffu, p[1], o);
            p[2] += __shfl_down_sync(0xffffffffu, p[2], o);
            p[3] += __shfl_down_sync(0xffffffffu, p[3], o);
        }
        if (lane == 0) {
#pragma unroll
            for (int u = 0; u < 4; u++) {
                const int ii = i0 + 16 * u;
                lg[l0 + ii + 1] = mk_s[ii] ? p[u] * scale : -1e30f;
            }
        }
    }
}

// ---------------------------------------------------------------------------
// attention stage 2: softmax in place, probs scaled by 1/sum and g_mask.
// 512 threads.
// ---------------------------------------------------------------------------
__global__ __launch_bounds__(512) void softmax_kernel(const int* __restrict__ gmask) {
    __shared__ float red[512];
    const int b   = blockIdx.x >> 3;
    const int h   = blockIdx.x & 7;
    const int tid = threadIdx.x;
    float* lg = g_lg + (b * Hh + h) * LGS;

    float lm = -1e30f;
    for (int j = tid; j < LGS; j += 512) lm = fmaxf(lm, lg[j]);
    red[tid] = lm;
    __syncthreads();
    for (int s = 256; s; s >>= 1) {
        if (tid < s) red[tid] = fmaxf(red[tid], red[tid + s]);
        __syncthreads();
    }
    const float mx = red[0];
    __syncthreads();

    float ls = 0.f;
    float ev[5];
    int nv = 0;
    for (int j = tid; j < LGS; j += 512) {
        float e = expf(lg[j] - mx);
        ev[nv++] = e;
        ls += e;
    }
    red[tid] = ls;
    __syncthreads();
    for (int s = 256; s; s >>= 1) {
        if (tid < s) red[tid] += red[tid + s];
        __syncthreads();
    }
    const float fac = (1.0f / red[0]) * (float)gmask[b];
    nv = 0;
    for (int j = tid; j < LGS; j += 512) lg[j] = ev[nv++] * fac;
}

// ---------------------------------------------------------------------------
// attention stage 3: weighted V sum partials. grid = 32*8*8 (b, h, slice).
// Key 0 peeled to slice 0 / grp 0; 4-key unroll (MLP 16).
// ---------------------------------------------------------------------------
__global__ __launch_bounds__(256) void vsum_kernel() {
    __shared__ float red[256];
    const int bid   = blockIdx.x;
    const int slice = bid & 7;
    const int h     = (bid >> 3) & 7;
    const int b     = bid >> 6;
    const int tid   = threadIdx.x;
    const int d     = tid & 63;
    const int grp   = tid >> 6;
    const int l0    = slice * 256;

    const __half* Yv = g_Yh + (size_t)b * Ll * KVW + 512 + h * HDd + d;
    const float* lg = g_lg + (b * Hh + h) * LGS;

    float acc = 0.f;
    if (slice == 0 && grp == 0)
        acc = lg[0] * g_cmax[b * MCH + 1024 + h * HDd + d];

#pragma unroll
    for (int it = 0; it < 16; it++) {
        const int i0 = grp + 16 * it;        // keys i0, i0+4, i0+8, i0+12
        float v[4];
#pragma unroll
        for (int u = 0; u < 4; u++) {
            const int l = l0 + i0 + 4 * u;
            const __half* r = Yv + (size_t)l * KVW;
            __half hv = r[0];
            if (l > 0)      hv = __hmax(hv, r[-KVW]);
            if (l < Ll - 1) hv = __hmax(hv, r[KVW]);
            v[u] = __half2float(hv);
        }
#pragma unroll
        for (int u = 0; u < 4; u++)
            acc += lg[l0 + i0 + 4 * u + 1] * v[u];
    }
    red[tid] = acc;
    __syncthreads();
    if (tid < 64) {
        float o = red[tid] + red[tid + 64] + red[tid + 128] + red[tid + 192];
        g_part[((b * Hh + h) * NSL + slice) * HDd + d] = o;
    }
}

// ---------------------------------------------------------------------------
// final: reduce slice partials, head-mix (Wh 8x8), output 1x1 conv (Wo).
// ---------------------------------------------------------------------------
__global__ __launch_bounds__(512) void final_kernel(const float* __restrict__ Wh,
                                                    const float* __restrict__ bh,
                                                    const float* __restrict__ Wo,
                                                    const float* __restrict__ bo,
                                                    float* __restrict__ out) {
    const int b    = blockIdx.x;
    const int quad = blockIdx.y;
    const int tid  = threadIdx.x;
    __shared__ float att_s[512];
    __shared__ float mid[512];

    {
        const int h = tid >> 6, d = tid & 63;
        const float* p = g_part + ((b * Hh + h) * NSL) * HDd + d;
        float s = 0.f;
#pragma unroll
        for (int sl = 0; sl < NSL; sl++) s += p[sl * HDd];
        att_s[tid] = s;
    }
    __syncthreads();

    {
        const int oh = tid >> 6, d = tid & 63;
        float s = bh[oh];
#pragma unroll
        for (int i = 0; i < 8; i++) s += Wh[oh * 8 + i] * att_s[i * HDd + d];
        mid[tid] = s;
    }
    __syncthreads();

    const int o    = quad * 128 + (tid >> 2);
    const int part = tid & 3;
    const float* wr = Wo + (size_t)o * 512 + part * 128;
    const float* mr = mid + part * 128;
    float s = 0.f;
#pragma unroll 16
    for (int i = 0; i < 128; i++) s += wr[i] * mr[i];
    s += __shfl_xor_sync(0xffffffffu, s, 1);
    s += __shfl_xor_sync(0xffffffffu, s, 2);
    if (part == 0) out[b * 512 + o] = s + bo[o];
}

// ---------------------------------------------------------------------------
// Launch
// ---------------------------------------------------------------------------
extern "C" void kernel_launch(void* const* d_in, const int* in_sizes, int n_in,
                              void* d_out, int out_size) {
    const float* t     = (const float*)d_in[0];
    const int*   gmask = (const int*)d_in[2];
    const int*   tmask = (const int*)d_in[3];
    const float* Wq    = (const float*)d_in[4];
    const float* bq    = (const float*)d_in[5];
    const float* Wk    = (const float*)d_in[6];
    const float* bk    = (const float*)d_in[7];
    const float* Wv    = (const float*)d_in[8];
    const float* bv    = (const float*)d_in[9];
    const float* Wh    = (const float*)d_in[10];
    const float* bh    = (const float*)d_in[11];
    const float* Wo    = (const float*)d_in[12];
    const float* bo    = (const float*)d_in[13];
    float* out = (float*)d_out;

    cudaFuncSetAttribute(conv_wino_kernel, cudaFuncAttributeMaxDynamicSharedMemorySize,
                         NSTAGEW * STAGEW);

    vtrans_kernel<<<(NPAIR * 128 + 255) / 256, 256>>>(t);
    wtrans_kernel<<<(MCH * 512 + 255) / 256, 256>>>(Wq, bq, Wk, bk, Wv, bv);
    conv_wino_kernel<<<dim3(MCH / TNW, NPAIR / PB), 256, NSTAGEW * STAGEW>>>();
    logits_kernel<<<Bb * Hh * NSL, 256>>>(gmask, tmask);
    softmax_kernel<<<Bb * Hh, 512>>>(gmask);
    vsum_kernel<<<Bb * Hh * NSL, 256>>>();
    final_kernel<<<dim3(Bb, 4), 512>>>(Wh, bh, Wo, bo, out);
}

// round 12
// speedup vs baseline: 1.7699x; 1.0089x over previous
#include <cuda_runtime.h>
#include <cuda_fp16.h>
#include <cstdint>
#include <cstddef>

// Problem constants
#define Bb 32
#define Ll 2048
#define Uu 512
#define Hh 8
#define HDd 64
#define NPOS (Bb * Ll)      // 65536
#define MCH 1536            // q|k|v channels (cmax indexing)
#define KVW 1024            // stored channels (k,v only), fp16
#define LGS 2049            // logits per (b,h)
#define NSL 8               // attention slices
#define NPAIR 32768         // Winograd output pairs (NPOS/2)

// Winograd GEMM config: M = pairs, N = channels, K = 512 per g, 4 g's
#define PB 128              // pairs per block tile
#define TNW 128             // channels per block tile
#define BKW 64
#define NSUPER 16           // superchunks (2 k-chunks each)
#define TILE16K 16384
#define STAGEW 65536        // [A0|B0|A1|B1]
#define NSTAGEW 3           // 192KB total

#define VPB 16              // vtrans pairs per block

// ---------------------------------------------------------------------------
// Device scratch
// ---------------------------------------------------------------------------
__device__ __align__(16) __half g_V[4ull * NPAIR * 512];      // Winograd inputs, 128MB
__device__ __align__(16) __half g_U[4ull * MCH * 512];        // Winograd weights (U3 negated)
__device__ __align__(16) __half g_Yh[(size_t)NPOS * KVW];     // k|v conv out fp16, 128MB
__device__ float g_bias[MCH];
__device__ float g_cmax[Bb * MCH];
__device__ float g_lg[Bb * Hh * LGS];                         // logits -> probs
__device__ float g_part[Bb * Hh * NSL * HDd];                 // V partial sums

// ---------------------------------------------------------------------------
// Helpers
// ---------------------------------------------------------------------------
__device__ __forceinline__ void cp16(uint32_t dst, const void* src) {
    asm volatile("cp.async.cg.shared.global [%0], [%1], 16;\n"
                 :: "r"(dst), "l"(src));
}
#define CP_COMMIT() asm volatile("cp.async.commit_group;" ::: "memory")
#define CP_WAIT(n)  asm volatile("cp.async.wait_group %0;" :: "n"(n) : "memory")

__device__ __forceinline__ uint32_t su32(const void* p) {
    uint32_t a;
    asm("{ .reg .u64 t; cvta.to.shared.u64 t, %1; cvt.u32.u64 %0, t; }" : "=r"(a) : "l"(p));
    return a;
}

__device__ __forceinline__ void mma_f16(float c[4],
                                        uint32_t a0, uint32_t a1, uint32_t a2, uint32_t a3,
                                        uint32_t b0, uint32_t b1) {
    asm volatile(
        "mma.sync.aligned.m16n8k16.row.col.f32.f16.f16.f32 "
        "{%0,%1,%2,%3}, {%4,%5,%6,%7}, {%8,%9}, {%0,%1,%2,%3};\n"
        : "+f"(c[0]), "+f"(c[1]), "+f"(c[2]), "+f"(c[3])
        : "r"(a0), "r"(a1), "r"(a2), "r"(a3), "r"(b0), "r"(b1));
}

#define LDSM_X4(r0, r1, r2, r3, addr)                                         \
    asm volatile("ldmatrix.sync.aligned.m8n8.x4.shared.b16 {%0,%1,%2,%3}, [%4];" \
                 : "=r"(r0), "=r"(r1), "=r"(r2), "=r"(r3) : "r"(addr))

__device__ __forceinline__ void atomicMaxF(float* a, float v) {
    if (v >= 0.f) atomicMax((int*)a, __float_as_int(v));
    else          atomicMin((unsigned*)a, __float_as_uint(v));
}

// ---------------------------------------------------------------------------
// Winograd input transform with smem row-sharing: 16 pairs x 128 ch per block.
// Rows 2*lp0-1 .. 2*lp0+32 (34 rows) loaded once; each pair reads 4 of them.
// ---------------------------------------------------------------------------
__global__ __launch_bounds__(256) void vtrans_kernel(const float* __restrict__ t) {
    __shared__ float rs[34][132];
    const int pb  = blockIdx.x;           // 0..2047
    const int cq  = blockIdx.y;           // 0..3 channel quarters
    const int p0  = pb * VPB;
    const int b   = p0 >> 10;
    const int lp0 = p0 & 1023;
    const int c0  = cq * 128;
    const int tid = threadIdx.x;

    const float* tb = t + (size_t)b * Ll * Uu + c0;
    for (int it = tid; it < 34 * 32; it += 256) {
        int r  = it >> 5;
        int c4 = (it & 31) << 2;
        int l  = 2 * lp0 - 1 + r;
        float4 v = make_float4(0.f, 0.f, 0.f, 0.f);
        if (l >= 0 && l < Ll) v = *(const float4*)(tb + (size_t)l * Uu + c4);
        *(float4*)&rs[r][c4] = v;
    }
    __syncthreads();

    for (int it = tid; it < VPB * 32; it += 256) {
        int pp = it >> 5;
        int c4 = (it & 31) << 2;
        float4 w0 = *(float4*)&rs[2 * pp][c4];
        float4 w1 = *(float4*)&rs[2 * pp + 1][c4];
        float4 w2 = *(float4*)&rs[2 * pp + 2][c4];
        float4 w3 = *(float4*)&rs[2 * pp + 3][c4];
        const size_t eo = (size_t)(p0 + pp) * 512 + c0 + c4;
        auto st = [&](int g, float a, float bb, float c, float d) {
            __half2 lo = __floats2half2_rn(a, bb);
            __half2 hi = __floats2half2_rn(c, d);
            *(uint2*)(g_V + (size_t)g * NPAIR * 512 + eo) =
                make_uint2(*(uint32_t*)&lo, *(uint32_t*)&hi);
        };
        st(0, w0.x - w2.x, w0.y - w2.y, w0.z - w2.z, w0.w - w2.w);
        st(1, w1.x + w2.x, w1.y + w2.y, w1.z + w2.z, w1.w + w2.w);
        st(2, w2.x - w1.x, w2.y - w1.y, w2.z - w1.z, w2.w - w1.w);
        st(3, w1.x - w3.x, w1.y - w3.y, w1.z - w3.z, w1.w - w3.w);
    }
}

// ---------------------------------------------------------------------------
// Winograd weight transform (U3 stored NEGATED so g3 mma's directly into y1).
// Also: bias fill + cmax init (merged).
// ---------------------------------------------------------------------------
__global__ __launch_bounds__(256) void wtrans_kernel(
        const float* __restrict__ Wq, const float* __restrict__ bq,
        const float* __restrict__ Wk, const float* __restrict__ bk,
        const float* __restrict__ Wv, const float* __restrict__ bv) {
    int gid = blockIdx.x * 256 + threadIdx.x;
    if (gid < MCH)
        g_bias[gid] = gid < 512 ? bq[gid] : (gid < 1024 ? bk[gid - 512] : bv[gid - 1024]);
    if (gid < Bb * MCH) ((unsigned*)g_cmax)[gid] = 0xff800000u;   // -inf
    if (gid >= MCH * 512) return;
    const int mg = gid / 512;
    const int k  = gid % 512;
    const int conv = mg / 512;
    const int m    = mg % 512;
    const float* W = (conv == 0) ? Wq : ((conv == 1) ? Wk : Wv);
    const float g0 = W[m * 1536 + k * 3 + 0];
    const float g1 = W[m * 1536 + k * 3 + 1];
    const float g2 = W[m * 1536 + k * 3 + 2];
    const size_t eo = (size_t)mg * 512 + k;
    g_U[0ull * MCH * 512 + eo] = __float2half_rn(g0);
    g_U[1ull * MCH * 512 + eo] = __float2half_rn(0.5f * (g0 + g1 + g2));
    g_U[2ull * MCH * 512 + eo] = __float2half_rn(0.5f * (g0 - g1 + g2));
    g_U[3ull * MCH * 512 + eo] = __float2half_rn(-g2);           // NEGATED
}

// ---------------------------------------------------------------------------
// Winograd conv GEMM (unchanged from banked best)
// ---------------------------------------------------------------------------
__global__ __launch_bounds__(256, 1) void conv_wino_kernel() {
    extern __shared__ __align__(128) char dsmem[];   // 3 * 64KB
    __shared__ float bias_s[TNW];

    const int tid  = threadIdx.x;
    const int wid  = tid >> 5;
    const int lane = tid & 31;
    const int gr   = lane >> 2;
    const int tg   = lane & 3;
    const int wp   = wid & 1;           // 2 warps over pairs (64 each)
    const int wc   = wid >> 1;          // 4 warps over channels (32 each)
    const int m0    = blockIdx.x * TNW;
    const int pair0 = blockIdx.y * PB;
    const int b     = pair0 >> 10;

    if (tid < TNW) bias_s[tid] = g_bias[m0 + tid];

    const uint32_t smem0 = su32(dsmem);

    auto load_chunk = [&](int c, uint32_t cbase) {
        const int g  = c >> 3;
        const int k0 = (c & 7) * BKW;
#pragma unroll
        for (int p = 0; p < 4; p++) {           // A: 128 rows x 8 chunks
            int idx = p * 256 + tid;
            int row = idx >> 3;
            int j   = idx & 7;
            const void* src = g_V + (size_t)g * NPAIR * 512
                              + (size_t)(pair0 + row) * 512 + k0 + j * 8;
            cp16(cbase + (uint32_t)(row * 128 + ((j ^ (row & 7)) << 4)), src);
        }
#pragma unroll
        for (int p = 0; p < 4; p++) {           // B: 128 rows x 8 chunks
            int idx = p * 256 + tid;
            int row = idx >> 3;
            int j   = idx & 7;
            const void* src = g_U + (size_t)g * MCH * 512
                              + (size_t)(m0 + row) * 512 + k0 + j * 8;
            cp16(cbase + TILE16K + (uint32_t)(row * 128 + ((j ^ (row & 7)) << 4)), src);
        }
    };
    auto load_super = [&](int s, int slot) {
        const uint32_t base = smem0 + (uint32_t)slot * STAGEW;
        load_chunk(2 * s,     base);
        load_chunk(2 * s + 1, base + 2u * TILE16K);
    };

    const int sub = lane >> 3;          // 0..3
    const int lr  = lane & 7;
    uint32_t aRowOff[4], bRowOff[2];
#pragma unroll
    for (int mt = 0; mt < 4; mt++)
        aRowOff[mt] = (uint32_t)((wp * 64 + mt * 16 + ((sub & 1) << 3) + lr) * 128);
#pragma unroll
    for (int p = 0; p < 2; p++)
        bRowOff[p] = (uint32_t)((wc * 32 + p * 16 + ((sub >> 1) << 3) + lr) * 128);
    const int aSub = sub >> 1;
    const int bSub = sub & 1;

    float y0[4][4][4], y1[4][4][4], macc[4][4][4];
#pragma unroll
    for (int i = 0; i < 4; i++)
#pragma unroll
        for (int j = 0; j < 4; j++)
#pragma unroll
            for (int e = 0; e < 4; e++) { y0[i][j][e] = 0.f; y1[i][j][e] = 0.f; macc[i][j][e] = 0.f; }

    auto compute_phase = [&](uint32_t abase, float (&acc)[4][4][4]) {
        const uint32_t bbase = abase + TILE16K;
#pragma unroll
        for (int kk = 0; kk < 4; kk++) {
            const uint32_t aCh = (uint32_t)(((2 * kk + aSub) ^ lr) << 4);
            const uint32_t bCh = (uint32_t)(((2 * kk + bSub) ^ lr) << 4);
            uint32_t a[4][4];
#pragma unroll
            for (int mt = 0; mt < 4; mt++)
                LDSM_X4(a[mt][0], a[mt][1], a[mt][2], a[mt][3],
                        abase + aRowOff[mt] + aCh);
            uint32_t bf[4][2];
#pragma unroll
            for (int p = 0; p < 2; p++)
                LDSM_X4(bf[2 * p][0], bf[2 * p][1], bf[2 * p + 1][0], bf[2 * p + 1][1],
                        bbase + bRowOff[p] + bCh);
#pragma unroll
            for (int mt = 0; mt < 4; mt++)
#pragma unroll
                for (int nt = 0; nt < 4; nt++)
                    mma_f16(acc[mt][nt], a[mt][0], a[mt][1], a[mt][2], a[mt][3],
                            bf[nt][0], bf[nt][1]);
        }
    };

    load_super(0, 0); CP_COMMIT();
    load_super(1, 1); CP_COMMIT();

    for (int s = 0; s < NSUPER; s++) {
        if (s + 1 < NSUPER) { CP_WAIT(1); } else { CP_WAIT(0); }
        __syncthreads();
        if (s + 2 < NSUPER) { load_super(s + 2, (s + 2) % NSTAGEW); CP_COMMIT(); }

        const uint32_t base = smem0 + (uint32_t)(s % NSTAGEW) * STAGEW;
        const int g = s >> 2;
        if (g == 0) {
            compute_phase(base, y0);
            compute_phase(base + 2u * TILE16K, y0);
        } else if (g == 1) {
            compute_phase(base, macc);
            compute_phase(base + 2u * TILE16K, macc);
            if (s == 7) {
#pragma unroll
                for (int mt = 0; mt < 4; mt++)
#pragma unroll
                    for (int nt = 0; nt < 4; nt++)
#pragma unroll
                        for (int e = 0; e < 4; e++) {
                            y0[mt][nt][e] += macc[mt][nt][e];
                            y1[mt][nt][e] += macc[mt][nt][e];
                            macc[mt][nt][e] = 0.f;
                        }
            }
        } else if (g == 2) {
            compute_phase(base, macc);
            compute_phase(base + 2u * TILE16K, macc);
            if (s == 11) {
#pragma unroll
                for (int mt = 0; mt < 4; mt++)
#pragma unroll
                    for (int nt = 0; nt < 4; nt++)
#pragma unroll
                        for (int e = 0; e < 4; e++) {
                            y0[mt][nt][e] += macc[mt][nt][e];
                            y1[mt][nt][e] -= macc[mt][nt][e];
                        }
            }
        } else {
            compute_phase(base, y1);
            compute_phase(base + 2u * TILE16K, y1);
        }
    }

    const bool do_store = (m0 >= 512);
#pragma unroll
    for (int nt = 0; nt < 4; nt++) {
        const int ch = m0 + wc * 32 + nt * 8 + 2 * tg;
        const float b0 = bias_s[ch - m0], b1 = bias_s[ch - m0 + 1];
        float cm0 = -3.4e38f, cm1 = -3.4e38f;
#pragma unroll
        for (int mt = 0; mt < 4; mt++) {
            const int P = pair0 + wp * 64 + mt * 16 + gr;
            float v00 = y0[mt][nt][0] + b0, v01 = y0[mt][nt][1] + b1;
            float w00 = y1[mt][nt][0] + b0, w01 = y1[mt][nt][1] + b1;
            float v10 = y0[mt][nt][2] + b0, v11 = y0[mt][nt][3] + b1;
            float w10 = y1[mt][nt][2] + b0, w11 = y1[mt][nt][3] + b1;
            if (do_store) {
                __half* base = g_Yh + (size_t)(2 * P) * KVW + (ch - 512);
                *(__half2*)(base)                    = __floats2half2_rn(v00, v01);
                *(__half2*)(base + KVW)              = __floats2half2_rn(w00, w01);
                *(__half2*)(base + (size_t)16 * KVW) = __floats2half2_rn(v10, v11);
                *(__half2*)(base + (size_t)17 * KVW) = __floats2half2_rn(w10, w11);
            }
            cm0 = fmaxf(cm0, fmaxf(fmaxf(v00, w00), fmaxf(v10, w10)));
            cm1 = fmaxf(cm1, fmaxf(fmaxf(v01, w01), fmaxf(v11, w11)));
        }
#pragma unroll
        for (int o = 4; o <= 16; o <<= 1) {
            cm0 = fmaxf(cm0, __shfl_xor_sync(0xffffffffu, cm0, o));
            cm1 = fmaxf(cm1, __shfl_xor_sync(0xffffffffu, cm1, o));
        }
        if (lane < 4) {
            atomicMaxF(&g_cmax[b * MCH + ch], cm0);
            atomicMaxF(&g_cmax[b * MCH + ch + 1], cm1);
        }
    }
}

// ---------------------------------------------------------------------------
// attention stage 1: raw masked logits. grid = 32*8*8 (b, h, slice).
// Warp w covers 32 CONSECUTIVE keys [l0+w*32, +32); 8 keys per iteration
// share rows: 10 row loads for 8 maxpool windows. Edge rows clamp-replicate
// (equivalent to -inf-padded maxpool). Full 256-key coverage per slice.
// ---------------------------------------------------------------------------
__global__ __launch_bounds__(256) void logits_kernel(const int* __restrict__ gmask,
                                                     const int* __restrict__ tmask) {
    __shared__ float q_s[64];
    __shared__ int   mk_s[256];
    const int bid   = blockIdx.x;
    const int slice = bid & 7;
    const int h     = (bid >> 3) & 7;
    const int b     = bid >> 6;
    const int tid   = threadIdx.x;
    const int lane  = tid & 31;
    const int w     = tid >> 5;          // 0..7
    const int l0    = slice * 256;

    if (tid < 64) q_s[tid] = g_cmax[b * MCH + h * HDd + tid];
    mk_s[tid] = tmask[b * Ll + l0 + tid];
    __syncthreads();

    const float scale = 0.04419417382415922f;   // 1/sqrt(512)
    float* lg = g_lg + (b * Hh + h) * LGS;
    const float qa = q_s[2 * lane], qb = q_s[2 * lane + 1];
    const __half2* Y2 = (const __half2*)(g_Yh + (size_t)b * Ll * KVW + h * HDd) + lane;

    if (slice == 0 && w == 0) {   // key 0: global max key
        float k0f = g_cmax[b * MCH + 512 + h * HDd + 2 * lane];
        float k1f = g_cmax[b * MCH + 512 + h * HDd + 2 * lane + 1];
        float p = qa * k0f + qb * k1f;
#pragma unroll
        for (int o = 16; o; o >>= 1) p += __shfl_down_sync(0xffffffffu, p, o);
        if (lane == 0) lg[0] = gmask[b] ? p * scale : -1e30f;
    }

    const int L0 = l0 + w * 32;
#pragma unroll
    for (int it = 0; it < 4; it++) {
        const int lb = L0 + it * 8;          // keys lb..lb+7
        __half2 r[10];
#pragma unroll
        for (int u = 0; u < 10; u++) {
            int l = lb - 1 + u;
            l = l < 0 ? 0 : (l > Ll - 1 ? Ll - 1 : l);
            r[u] = Y2[(size_t)l * (KVW / 2)];
        }
        float p[8];
#pragma unroll
        for (int u = 0; u < 8; u++) {
            __half2 kv = __hmax2(__hmax2(r[u], r[u + 1]), r[u + 2]);
            float2 f = __half22float2(kv);
            p[u] = qa * f.x + qb * f.y;
        }
#pragma unroll
        for (int o = 16; o; o >>= 1) {
#pragma unroll
            for (int u = 0; u < 8; u++)
                p[u] += __shfl_down_sync(0xffffffffu, p[u], o);
        }
        if (lane == 0) {
#pragma unroll
            for (int u = 0; u < 8; u++) {
                const int ii = lb - l0 + u;
                lg[lb + u + 1] = mk_s[ii] ? p[u] * scale : -1e30f;
            }
        }
    }
}

// ---------------------------------------------------------------------------
// attention stage 2: softmax in place, probs scaled by 1/sum and g_mask.
// ---------------------------------------------------------------------------
__global__ __launch_bounds__(512) void softmax_kernel(const int* __restrict__ gmask) {
    __shared__ float red[512];
    const int b   = blockIdx.x >> 3;
    const int h   = blockIdx.x & 7;
    const int tid = threadIdx.x;
    float* lg = g_lg + (b * Hh + h) * LGS;

    float lm = -1e30f;
    for (int j = tid; j < LGS; j += 512) lm = fmaxf(lm, lg[j]);
    red[tid] = lm;
    __syncthreads();
    for (int s = 256; s; s >>= 1) {
        if (tid < s) red[tid] = fmaxf(red[tid], red[tid + s]);
        __syncthreads();
    }
    const float mx = red[0];
    __syncthreads();

    float ls = 0.f;
    float ev[5];
    int nv = 0;
    for (int j = tid; j < LGS; j += 512) {
        float e = expf(lg[j] - mx);
        ev[nv++] = e;
        ls += e;
    }
    red[tid] = ls;
    __syncthreads();
    for (int s = 256; s; s >>= 1) {
        if (tid < s) red[tid] += red[tid + s];
        __syncthreads();
    }
    const float fac = (1.0f / red[0]) * (float)gmask[b];
    nv = 0;
    for (int j = tid; j < LGS; j += 512) lg[j] = ev[nv++] * fac;
}

// ---------------------------------------------------------------------------
// attention stage 3: weighted V sum partials. grid = 32*8*8 (b, h, slice).
// Group grp covers 64 CONSECUTIVE keys; 8 keys per iteration share rows
// (10 loads per 8 windows, clamp-replicate edges). Key 0 peeled.
// ---------------------------------------------------------------------------
__global__ __launch_bounds__(256) void vsum_kernel() {
    __shared__ float red[256];
    const int bid   = blockIdx.x;
    const int slice = bid & 7;
    const int h     = (bid >> 3) & 7;
    const int b     = bid >> 6;
    const int tid   = threadIdx.x;
    const int d     = tid & 63;
    const int grp   = tid >> 6;
    const int l0    = slice * 256;

    const __half* Yv = g_Yh + (size_t)b * Ll * KVW + 512 + h * HDd + d;
    const float* lg = g_lg + (b * Hh + h) * LGS;

    float acc = 0.f;
    if (slice == 0 && grp == 0)
        acc = lg[0] * g_cmax[b * MCH + 1024 + h * HDd + d];

    const int L0 = l0 + grp * 64;
#pragma unroll
    for (int it = 0; it < 8; it++) {
        const int lb = L0 + it * 8;          // keys lb..lb+7
        __half r[10];
#pragma unroll
        for (int u = 0; u < 10; u++) {
            int l = lb - 1 + u;
            l = l < 0 ? 0 : (l > Ll - 1 ? Ll - 1 : l);
            r[u] = Yv[(size_t)l * KVW];
        }
#pragma unroll
        for (int u = 0; u < 8; u++) {
            __half hv = __hmax(__hmax(r[u], r[u + 1]), r[u + 2]);
            acc += lg[lb + u + 1] * __half2float(hv);
        }
    }
    red[tid] = acc;
    __syncthreads();
    if (tid < 64) {
        float o = red[tid] + red[tid + 64] + red[tid + 128] + red[tid + 192];
        g_part[((b * Hh + h) * NSL + slice) * HDd + d] = o;
    }
}

// ---------------------------------------------------------------------------
// final: reduce slice partials, head-mix (Wh 8x8), output 1x1 conv (Wo).
// ---------------------------------------------------------------------------
__global__ __launch_bounds__(512) void final_kernel(const float* __restrict__ Wh,
                                                    const float* __restrict__ bh,
                                                    const float* __restrict__ Wo,
                                                    const float* __restrict__ bo,
                                                    float* __restrict__ out) {
    const int b    = blockIdx.x;
    const int quad = blockIdx.y;
    const int tid  = threadIdx.x;
    __shared__ float att_s[512];
    __shared__ float mid[512];

    {
        const int h = tid >> 6, d = tid & 63;
        const float* p = g_part + ((b * Hh + h) * NSL) * HDd + d;
        float s = 0.f;
#pragma unroll
        for (int sl = 0; sl < NSL; sl++) s += p[sl * HDd];
        att_s[tid] = s;
    }
    __syncthreads();

    {
        const int oh = tid >> 6, d = tid & 63;
        float s = bh[oh];
#pragma unroll
        for (int i = 0; i < 8; i++) s += Wh[oh * 8 + i] * att_s[i * HDd + d];
        mid[tid] = s;
    }
    __syncthreads();

    const int o    = quad * 128 + (tid >> 2);
    const int part = tid & 3;
    const float* wr = Wo + (size_t)o * 512 + part * 128;
    const float* mr = mid + part * 128;
    float s = 0.f;
#pragma unroll 16
    for (int i = 0; i < 128; i++) s += wr[i] * mr[i];
    s += __shfl_xor_sync(0xffffffffu, s, 1);
    s += __shfl_xor_sync(0xffffffffu, s, 2);
    if (part == 0) out[b * 512 + o] = s + bo[o];
}

// ---------------------------------------------------------------------------
// Launch
// ---------------------------------------------------------------------------
extern "C" void kernel_launch(void* const* d_in, const int* in_sizes, int n_in,
                              void* d_out, int out_size) {
    const float* t     = (const float*)d_in[0];
    const int*   gmask = (const int*)d_in[2];
    const int*   tmask = (const int*)d_in[3];
    const float* Wq    = (const float*)d_in[4];
    const float* bq    = (const float*)d_in[5];
    const float* Wk    = (const float*)d_in[6];
    const float* bk    = (const float*)d_in[7];
    const float* Wv    = (const float*)d_in[8];
    const float* bv    = (const float*)d_in[9];
    const float* Wh    = (const float*)d_in[10];
    const float* bh    = (const float*)d_in[11];
    const float* Wo    = (const float*)d_in[12];
    const float* bo    = (const float*)d_in[13];
    float* out = (float*)d_out;

    cudaFuncSetAttribute(conv_wino_kernel, cudaFuncAttributeMaxDynamicSharedMemorySize,
                         NSTAGEW * STAGEW);

    vtrans_kernel<<<dim3(NPAIR / VPB, 4), 256>>>(t);
    wtrans_kernel<<<(MCH * 512 + 255) / 256, 256>>>(Wq, bq, Wk, bk, Wv, bv);
    conv_wino_kernel<<<dim3(MCH / TNW, NPAIR / PB), 256, NSTAGEW * STAGEW>>>();
    logits_kernel<<<Bb * Hh * NSL, 256>>>(gmask, tmask);
    softmax_kernel<<<Bb * Hh, 512>>>(gmask);
    vsum_kernel<<<Bb * Hh * NSL, 256>>>();
    final_kernel<<<dim3(Bb, 4), 512>>>(Wh, bh, Wo, bo, out);
}

// round 13
// speedup vs baseline: 1.7791x; 1.0052x over previous
#include <cuda_runtime.h>
#include <cuda_fp16.h>
#include <cstdint>
#include <cstddef>

// Problem constants
#define Bb 32
#define Ll 2048
#define Uu 512
#define Hh 8
#define HDd 64
#define NPOS (Bb * Ll)      // 65536
#define MCH 1536            // q|k|v channels (cmax indexing)
#define KVW 1024            // stored channels (k,v only), fp16
#define LGS 2049            // logits per (b,h)
#define NSL 16              // attention slices (128 keys each)
#define NPAIR 32768         // Winograd output pairs (NPOS/2)

// Winograd GEMM config: M = pairs, N = channels, K = 512 per g, 4 g's
#define PB 128              // pairs per block tile
#define TNW 128             // channels per block tile
#define BKW 64
#define NSUPER 16           // superchunks (2 k-chunks each)
#define TILE16K 16384
#define STAGEW 65536        // [A0|B0|A1|B1]
#define NSTAGEW 3           // 192KB total

#define VPB 16              // vtrans pairs per block

// ---------------------------------------------------------------------------
// Device scratch
// ---------------------------------------------------------------------------
__device__ __align__(16) __half g_V[4ull * NPAIR * 512];      // Winograd inputs, 128MB
__device__ __align__(16) __half g_U[4ull * MCH * 512];        // Winograd weights (U3 negated)
__device__ __align__(16) __half g_Yh[(size_t)NPOS * KVW];     // k|v conv out fp16, 128MB
__device__ float g_bias[MCH];
__device__ float g_cmax[Bb * MCH];
__device__ float g_lg[Bb * Hh * LGS];                         // logits -> probs
__device__ float g_part[Bb * Hh * NSL * HDd];                 // V partial sums

// ---------------------------------------------------------------------------
// Helpers
// ---------------------------------------------------------------------------
__device__ __forceinline__ void cp16(uint32_t dst, const void* src) {
    asm volatile("cp.async.cg.shared.global [%0], [%1], 16;\n"
                 :: "r"(dst), "l"(src));
}
#define CP_COMMIT() asm volatile("cp.async.commit_group;" ::: "memory")
#define CP_WAIT(n)  asm volatile("cp.async.wait_group %0;" :: "n"(n) : "memory")

__device__ __forceinline__ uint32_t su32(const void* p) {
    uint32_t a;
    asm("{ .reg .u64 t; cvta.to.shared.u64 t, %1; cvt.u32.u64 %0, t; }" : "=r"(a) : "l"(p));
    return a;
}

__device__ __forceinline__ void mma_f16(float c[4],
                                        uint32_t a0, uint32_t a1, uint32_t a2, uint32_t a3,
                                        uint32_t b0, uint32_t b1) {
    asm volatile(
        "mma.sync.aligned.m16n8k16.row.col.f32.f16.f16.f32 "
        "{%0,%1,%2,%3}, {%4,%5,%6,%7}, {%8,%9}, {%0,%1,%2,%3};\n"
        : "+f"(c[0]), "+f"(c[1]), "+f"(c[2]), "+f"(c[3])
        : "r"(a0), "r"(a1), "r"(a2), "r"(a3), "r"(b0), "r"(b1));
}

#define LDSM_X4(r0, r1, r2, r3, addr)                                         \
    asm volatile("ldmatrix.sync.aligned.m8n8.x4.shared.b16 {%0,%1,%2,%3}, [%4];" \
                 : "=r"(r0), "=r"(r1), "=r"(r2), "=r"(r3) : "r"(addr))

__device__ __forceinline__ void atomicMaxF(float* a, float v) {
    if (v >= 0.f) atomicMax((int*)a, __float_as_int(v));
    else          atomicMin((unsigned*)a, __float_as_uint(v));
}

// ---------------------------------------------------------------------------
// Winograd input transform with smem row-sharing: 16 pairs x 128 ch per block.
// ---------------------------------------------------------------------------
__global__ __launch_bounds__(256) void vtrans_kernel(const float* __restrict__ t) {
    __shared__ float rs[34][132];
    const int pb  = blockIdx.x;           // 0..2047
    const int cq  = blockIdx.y;           // 0..3 channel quarters
    const int p0  = pb * VPB;
    const int b   = p0 >> 10;
    const int lp0 = p0 & 1023;
    const int c0  = cq * 128;
    const int tid = threadIdx.x;

    const float* tb = t + (size_t)b * Ll * Uu + c0;
    for (int it = tid; it < 34 * 32; it += 256) {
        int r  = it >> 5;
        int c4 = (it & 31) << 2;
        int l  = 2 * lp0 - 1 + r;
        float4 v = make_float4(0.f, 0.f, 0.f, 0.f);
        if (l >= 0 && l < Ll) v = *(const float4*)(tb + (size_t)l * Uu + c4);
        *(float4*)&rs[r][c4] = v;
    }
    __syncthreads();

    for (int it = tid; it < VPB * 32; it += 256) {
        int pp = it >> 5;
        int c4 = (it & 31) << 2;
        float4 w0 = *(float4*)&rs[2 * pp][c4];
        float4 w1 = *(float4*)&rs[2 * pp + 1][c4];
        float4 w2 = *(float4*)&rs[2 * pp + 2][c4];
        float4 w3 = *(float4*)&rs[2 * pp + 3][c4];
        const size_t eo = (size_t)(p0 + pp) * 512 + c0 + c4;
        auto st = [&](int g, float a, float bb, float c, float d) {
            __half2 lo = __floats2half2_rn(a, bb);
            __half2 hi = __floats2half2_rn(c, d);
            *(uint2*)(g_V + (size_t)g * NPAIR * 512 + eo) =
                make_uint2(*(uint32_t*)&lo, *(uint32_t*)&hi);
        };
        st(0, w0.x - w2.x, w0.y - w2.y, w0.z - w2.z, w0.w - w2.w);
        st(1, w1.x + w2.x, w1.y + w2.y, w1.z + w2.z, w1.w + w2.w);
        st(2, w2.x - w1.x, w2.y - w1.y, w2.z - w1.z, w2.w - w1.w);
        st(3, w1.x - w3.x, w1.y - w3.y, w1.z - w3.z, w1.w - w3.w);
    }
}

// ---------------------------------------------------------------------------
// Winograd weight transform (U3 NEGATED); bias fill + cmax init merged.
// ---------------------------------------------------------------------------
__global__ __launch_bounds__(256) void wtrans_kernel(
        const float* __restrict__ Wq, const float* __restrict__ bq,
        const float* __restrict__ Wk, const float* __restrict__ bk,
        const float* __restrict__ Wv, const float* __restrict__ bv) {
    int gid = blockIdx.x * 256 + threadIdx.x;
    if (gid < MCH)
        g_bias[gid] = gid < 512 ? bq[gid] : (gid < 1024 ? bk[gid - 512] : bv[gid - 1024]);
    if (gid < Bb * MCH) ((unsigned*)g_cmax)[gid] = 0xff800000u;   // -inf
    if (gid >= MCH * 512) return;
    const int mg = gid / 512;
    const int k  = gid % 512;
    const int conv = mg / 512;
    const int m    = mg % 512;
    const float* W = (conv == 0) ? Wq : ((conv == 1) ? Wk : Wv);
    const float g0 = W[m * 1536 + k * 3 + 0];
    const float g1 = W[m * 1536 + k * 3 + 1];
    const float g2 = W[m * 1536 + k * 3 + 2];
    const size_t eo = (size_t)mg * 512 + k;
    g_U[0ull * MCH * 512 + eo] = __float2half_rn(g0);
    g_U[1ull * MCH * 512 + eo] = __float2half_rn(0.5f * (g0 + g1 + g2));
    g_U[2ull * MCH * 512 + eo] = __float2half_rn(0.5f * (g0 - g1 + g2));
    g_U[3ull * MCH * 512 + eo] = __float2half_rn(-g2);           // NEGATED
}

// ---------------------------------------------------------------------------
// Winograd conv GEMM (unchanged from banked best)
// ---------------------------------------------------------------------------
__global__ __launch_bounds__(256, 1) void conv_wino_kernel() {
    extern __shared__ __align__(128) char dsmem[];   // 3 * 64KB
    __shared__ float bias_s[TNW];

    const int tid  = threadIdx.x;
    const int wid  = tid >> 5;
    const int lane = tid & 31;
    const int gr   = lane >> 2;
    const int tg   = lane & 3;
    const int wp   = wid & 1;           // 2 warps over pairs (64 each)
    const int wc   = wid >> 1;          // 4 warps over channels (32 each)
    const int m0    = blockIdx.x * TNW;
    const int pair0 = blockIdx.y * PB;
    const int b     = pair0 >> 10;

    if (tid < TNW) bias_s[tid] = g_bias[m0 + tid];

    const uint32_t smem0 = su32(dsmem);

    auto load_chunk = [&](int c, uint32_t cbase) {
        const int g  = c >> 3;
        const int k0 = (c & 7) * BKW;
#pragma unroll
        for (int p = 0; p < 4; p++) {           // A: 128 rows x 8 chunks
            int idx = p * 256 + tid;
            int row = idx >> 3;
            int j   = idx & 7;
            const void* src = g_V + (size_t)g * NPAIR * 512
                              + (size_t)(pair0 + row) * 512 + k0 + j * 8;
            cp16(cbase + (uint32_t)(row * 128 + ((j ^ (row & 7)) << 4)), src);
        }
#pragma unroll
        for (int p = 0; p < 4; p++) {           // B: 128 rows x 8 chunks
            int idx = p * 256 + tid;
            int row = idx >> 3;
            int j   = idx & 7;
            const void* src = g_U + (size_t)g * MCH * 512
                              + (size_t)(m0 + row) * 512 + k0 + j * 8;
            cp16(cbase + TILE16K + (uint32_t)(row * 128 + ((j ^ (row & 7)) << 4)), src);
        }
    };
    auto load_super = [&](int s, int slot) {
        const uint32_t base = smem0 + (uint32_t)slot * STAGEW;
        load_chunk(2 * s,     base);
        load_chunk(2 * s + 1, base + 2u * TILE16K);
    };

    const int sub = lane >> 3;          // 0..3
    const int lr  = lane & 7;
    uint32_t aRowOff[4], bRowOff[2];
#pragma unroll
    for (int mt = 0; mt < 4; mt++)
        aRowOff[mt] = (uint32_t)((wp * 64 + mt * 16 + ((sub & 1) << 3) + lr) * 128);
#pragma unroll
    for (int p = 0; p < 2; p++)
        bRowOff[p] = (uint32_t)((wc * 32 + p * 16 + ((sub >> 1) << 3) + lr) * 128);
    const int aSub = sub >> 1;
    const int bSub = sub & 1;

    float y0[4][4][4], y1[4][4][4], macc[4][4][4];
#pragma unroll
    for (int i = 0; i < 4; i++)
#pragma unroll
        for (int j = 0; j < 4; j++)
#pragma unroll
            for (int e = 0; e < 4; e++) { y0[i][j][e] = 0.f; y1[i][j][e] = 0.f; macc[i][j][e] = 0.f; }

    auto compute_phase = [&](uint32_t abase, float (&acc)[4][4][4]) {
        const uint32_t bbase = abase + TILE16K;
#pragma unroll
        for (int kk = 0; kk < 4; kk++) {
            const uint32_t aCh = (uint32_t)(((2 * kk + aSub) ^ lr) << 4);
            const uint32_t bCh = (uint32_t)(((2 * kk + bSub) ^ lr) << 4);
            uint32_t a[4][4];
#pragma unroll
            for (int mt = 0; mt < 4; mt++)
                LDSM_X4(a[mt][0], a[mt][1], a[mt][2], a[mt][3],
                        abase + aRowOff[mt] + aCh);
            uint32_t bf[4][2];
#pragma unroll
            for (int p = 0; p < 2; p++)
                LDSM_X4(bf[2 * p][0], bf[2 * p][1], bf[2 * p + 1][0], bf[2 * p + 1][1],
                        bbase + bRowOff[p] + bCh);
#pragma unroll
            for (int mt = 0; mt < 4; mt++)
#pragma unroll
                for (int nt = 0; nt < 4; nt++)
                    mma_f16(acc[mt][nt], a[mt][0], a[mt][1], a[mt][2], a[mt][3],
                            bf[nt][0], bf[nt][1]);
        }
    };

    load_super(0, 0); CP_COMMIT();
    load_super(1, 1); CP_COMMIT();

    for (int s = 0; s < NSUPER; s++) {
        if (s + 1 < NSUPER) { CP_WAIT(1); } else { CP_WAIT(0); }
        __syncthreads();
        if (s + 2 < NSUPER) { load_super(s + 2, (s + 2) % NSTAGEW); CP_COMMIT(); }

        const uint32_t base = smem0 + (uint32_t)(s % NSTAGEW) * STAGEW;
        const int g = s >> 2;
        if (g == 0) {
            compute_phase(base, y0);
            compute_phase(base + 2u * TILE16K, y0);
        } else if (g == 1) {
            compute_phase(base, macc);
            compute_phase(base + 2u * TILE16K, macc);
            if (s == 7) {
#pragma unroll
                for (int mt = 0; mt < 4; mt++)
#pragma unroll
                    for (int nt = 0; nt < 4; nt++)
#pragma unroll
                        for (int e = 0; e < 4; e++) {
                            y0[mt][nt][e] += macc[mt][nt][e];
                            y1[mt][nt][e] += macc[mt][nt][e];
                            macc[mt][nt][e] = 0.f;
                        }
            }
        } else if (g == 2) {
            compute_phase(base, macc);
            compute_phase(base + 2u * TILE16K, macc);
            if (s == 11) {
#pragma unroll
                for (int mt = 0; mt < 4; mt++)
#pragma unroll
                    for (int nt = 0; nt < 4; nt++)
#pragma unroll
                        for (int e = 0; e < 4; e++) {
                            y0[mt][nt][e] += macc[mt][nt][e];
                            y1[mt][nt][e] -= macc[mt][nt][e];
                        }
            }
        } else {
            compute_phase(base, y1);
            compute_phase(base + 2u * TILE16K, y1);
        }
    }

    const bool do_store = (m0 >= 512);
#pragma unroll
    for (int nt = 0; nt < 4; nt++) {
        const int ch = m0 + wc * 32 + nt * 8 + 2 * tg;
        const float b0 = bias_s[ch - m0], b1 = bias_s[ch - m0 + 1];
        float cm0 = -3.4e38f, cm1 = -3.4e38f;
#pragma unroll
        for (int mt = 0; mt < 4; mt++) {
            const int P = pair0 + wp * 64 + mt * 16 + gr;
            float v00 = y0[mt][nt][0] + b0, v01 = y0[mt][nt][1] + b1;
            float w00 = y1[mt][nt][0] + b0, w01 = y1[mt][nt][1] + b1;
            float v10 = y0[mt][nt][2] + b0, v11 = y0[mt][nt][3] + b1;
            float w10 = y1[mt][nt][2] + b0, w11 = y1[mt][nt][3] + b1;
            if (do_store) {
                __half* base = g_Yh + (size_t)(2 * P) * KVW + (ch - 512);
                *(__half2*)(base)                    = __floats2half2_rn(v00, v01);
                *(__half2*)(base + KVW)              = __floats2half2_rn(w00, w01);
                *(__half2*)(base + (size_t)16 * KVW) = __floats2half2_rn(v10, v11);
                *(__half2*)(base + (size_t)17 * KVW) = __floats2half2_rn(w10, w11);
            }
            cm0 = fmaxf(cm0, fmaxf(fmaxf(v00, w00), fmaxf(v10, w10)));
            cm1 = fmaxf(cm1, fmaxf(fmaxf(v01, w01), fmaxf(v11, w11)));
        }
#pragma unroll
        for (int o = 4; o <= 16; o <<= 1) {
            cm0 = fmaxf(cm0, __shfl_xor_sync(0xffffffffu, cm0, o));
            cm1 = fmaxf(cm1, __shfl_xor_sync(0xffffffffu, cm1, o));
        }
        if (lane < 4) {
            atomicMaxF(&g_cmax[b * MCH + ch], cm0);
            atomicMaxF(&g_cmax[b * MCH + ch + 1], cm1);
        }
    }
}

// ---------------------------------------------------------------------------
// attention stage 1: raw masked logits. grid = 32*8*16 (b, h, slice).
// Slice covers 128 keys; warp w covers 16 consecutive keys (2 iterations of
// 8 row-shared maxpool windows, clamp-replicated edges).
// ---------------------------------------------------------------------------
__global__ __launch_bounds__(256) void logits_kernel(const int* __restrict__ gmask,
                                                     const int* __restrict__ tmask) {
    __shared__ float q_s[64];
    __shared__ int   mk_s[128];
    const int bid   = blockIdx.x;
    const int slice = bid & 15;
    const int h     = (bid >> 4) & 7;
    const int b     = bid >> 7;
    const int tid   = threadIdx.x;
    const int lane  = tid & 31;
    const int w     = tid >> 5;          // 0..7
    const int l0    = slice * 128;

    if (tid < 64) q_s[tid] = g_cmax[b * MCH + h * HDd + tid];
    if (tid < 128) mk_s[tid] = tmask[b * Ll + l0 + tid];
    __syncthreads();

    const float scale = 0.04419417382415922f;   // 1/sqrt(512)
    float* lg = g_lg + (b * Hh + h) * LGS;
    const float qa = q_s[2 * lane], qb = q_s[2 * lane + 1];
    const __half2* Y2 = (const __half2*)(g_Yh + (size_t)b * Ll * KVW + h * HDd) + lane;

    if (slice == 0 && w == 0) {   // key 0: global max key
        float k0f = g_cmax[b * MCH + 512 + h * HDd + 2 * lane];
        float k1f = g_cmax[b * MCH + 512 + h * HDd + 2 * lane + 1];
        float p = qa * k0f + qb * k1f;
#pragma unroll
        for (int o = 16; o; o >>= 1) p += __shfl_down_sync(0xffffffffu, p, o);
        if (lane == 0) lg[0] = gmask[b] ? p * scale : -1e30f;
    }

    const int L0 = l0 + w * 16;
#pragma unroll
    for (int it = 0; it < 2; it++) {
        const int lb = L0 + it * 8;          // keys lb..lb+7
        __half2 r[10];
#pragma unroll
        for (int u = 0; u < 10; u++) {
            int l = lb - 1 + u;
            l = l < 0 ? 0 : (l > Ll - 1 ? Ll - 1 : l);
            r[u] = Y2[(size_t)l * (KVW / 2)];
        }
        float p[8];
#pragma unroll
        for (int u = 0; u < 8; u++) {
            __half2 kv = __hmax2(__hmax2(r[u], r[u + 1]), r[u + 2]);
            float2 f = __half22float2(kv);
            p[u] = qa * f.x + qb * f.y;
        }
#pragma unroll
        for (int o = 16; o; o >>= 1) {
#pragma unroll
            for (int u = 0; u < 8; u++)
                p[u] += __shfl_down_sync(0xffffffffu, p[u], o);
        }
        if (lane == 0) {
#pragma unroll
            for (int u = 0; u < 8; u++) {
                const int ii = lb - l0 + u;
                lg[lb + u + 1] = mk_s[ii] ? p[u] * scale : -1e30f;
            }
        }
    }
}

// ---------------------------------------------------------------------------
// attention stage 2: softmax in place, probs scaled by 1/sum and g_mask.
// ---------------------------------------------------------------------------
__global__ __launch_bounds__(512) void softmax_kernel(const int* __restrict__ gmask) {
    __shared__ float red[512];
    const int b   = blockIdx.x >> 3;
    const int h   = blockIdx.x & 7;
    const int tid = threadIdx.x;
    float* lg = g_lg + (b * Hh + h) * LGS;

    float lm = -1e30f;
    for (int j = tid; j < LGS; j += 512) lm = fmaxf(lm, lg[j]);
    red[tid] = lm;
    __syncthreads();
    for (int s = 256; s; s >>= 1) {
        if (tid < s) red[tid] = fmaxf(red[tid], red[tid + s]);
        __syncthreads();
    }
    const float mx = red[0];
    __syncthreads();

    float ls = 0.f;
    float ev[5];
    int nv = 0;
    for (int j = tid; j < LGS; j += 512) {
        float e = expf(lg[j] - mx);
        ev[nv++] = e;
        ls += e;
    }
    red[tid] = ls;
    __syncthreads();
    for (int s = 256; s; s >>= 1) {
        if (tid < s) red[tid] += red[tid + s];
        __syncthreads();
    }
    const float fac = (1.0f / red[0]) * (float)gmask[b];
    nv = 0;
    for (int j = tid; j < LGS; j += 512) lg[j] = ev[nv++] * fac;
}

// ---------------------------------------------------------------------------
// attention stage 3: weighted V sum partials. grid = 32*8*16 (b, h, slice).
// Slice covers 128 keys; group covers 32 consecutive keys (4 iterations of
// 8 row-shared windows). Key 0 peeled to slice 0 / grp 0.
// ---------------------------------------------------------------------------
__global__ __launch_bounds__(256) void vsum_kernel() {
    __shared__ float red[256];
    const int bid   = blockIdx.x;
    const int slice = bid & 15;
    const int h     = (bid >> 4) & 7;
    const int b     = bid >> 7;
    const int tid   = threadIdx.x;
    const int d     = tid & 63;
    const int grp   = tid >> 6;
    const int l0    = slice * 128;

    const __half* Yv = g_Yh + (size_t)b * Ll * KVW + 512 + h * HDd + d;
    const float* lg = g_lg + (b * Hh + h) * LGS;

    float acc = 0.f;
    if (slice == 0 && grp == 0)
        acc = lg[0] * g_cmax[b * MCH + 1024 + h * HDd + d];

    const int L0 = l0 + grp * 32;
#pragma unroll
    for (int it = 0; it < 4; it++) {
        const int lb = L0 + it * 8;          // keys lb..lb+7
        __half r[10];
#pragma unroll
        for (int u = 0; u < 10; u++) {
            int l = lb - 1 + u;
            l = l < 0 ? 0 : (l > Ll - 1 ? Ll - 1 : l);
            r[u] = Yv[(size_t)l * KVW];
        }
#pragma unroll
        for (int u = 0; u < 8; u++) {
            __half hv = __hmax(__hmax(r[u], r[u + 1]), r[u + 2]);
            acc += lg[lb + u + 1] * __half2float(hv);
        }
    }
    red[tid] = acc;
    __syncthreads();
    if (tid < 64) {
        float o = red[tid] + red[tid + 64] + red[tid + 128] + red[tid + 192];
        g_part[((b * Hh + h) * NSL + slice) * HDd + d] = o;
    }
}

// ---------------------------------------------------------------------------
// final: reduce slice partials, head-mix (Wh 8x8), output 1x1 conv (Wo).
// ---------------------------------------------------------------------------
__global__ __launch_bounds__(512) void final_kernel(const float* __restrict__ Wh,
                                                    const float* __restrict__ bh,
                                                    const float* __restrict__ Wo,
                                                    const float* __restrict__ bo,
                                                    float* __restrict__ out) {
    const int b    = blockIdx.x;
    const int quad = blockIdx.y;
    const int tid  = threadIdx.x;
    __shared__ float att_s[512];
    __shared__ float mid[512];

    {
        const int h = tid >> 6, d = tid & 63;
        const float* p = g_part + ((b * Hh + h) * NSL) * HDd + d;
        float s = 0.f;
#pragma unroll
        for (int sl = 0; sl < NSL; sl++) s += p[sl * HDd];
        att_s[tid] = s;
    }
    __syncthreads();

    {
        const int oh = tid >> 6, d = tid & 63;
        float s = bh[oh];
#pragma unroll
        for (int i = 0; i < 8; i++) s += Wh[oh * 8 + i] * att_s[i * HDd + d];
        mid[tid] = s;
    }
    __syncthreads();

    const int o    = quad * 128 + (tid >> 2);
    const int part = tid & 3;
    const float* wr = Wo + (size_t)o * 512 + part * 128;
    const float* mr = mid + part * 128;
    float s = 0.f;
#pragma unroll 16
    for (int i = 0; i < 128; i++) s += wr[i] * mr[i];
    s += __shfl_xor_sync(0xffffffffu, s, 1);
    s += __shfl_xor_sync(0xffffffffu, s, 2);
    if (part == 0) out[b * 512 + o] = s + bo[o];
}

// ---------------------------------------------------------------------------
// Launch
// ---------------------------------------------------------------------------
extern "C" void kernel_launch(void* const* d_in, const int* in_sizes, int n_in,
                              void* d_out, int out_size) {
    const float* t     = (const float*)d_in[0];
    const int*   gmask = (const int*)d_in[2];
    const int*   tmask = (const int*)d_in[3];
    const float* Wq    = (const float*)d_in[4];
    const float* bq    = (const float*)d_in[5];
    const float* Wk    = (const float*)d_in[6];
    const float* bk    = (const float*)d_in[7];
    const float* Wv    = (const float*)d_in[8];
    const float* bv    = (const float*)d_in[9];
    const float* Wh    = (const float*)d_in[10];
    const float* bh    = (const float*)d_in[11];
    const float* Wo    = (const float*)d_in[12];
    const float* bo    = (const float*)d_in[13];
    float* out = (float*)d_out;

    cudaFuncSetAttribute(conv_wino_kernel, cudaFuncAttributeMaxDynamicSharedMemorySize,
                         NSTAGEW * STAGEW);

    vtrans_kernel<<<dim3(NPAIR / VPB, 4), 256>>>(t);
    wtrans_kernel<<<(MCH * 512 + 255) / 256, 256>>>(Wq, bq, Wk, bk, Wv, bv);
    conv_wino_kernel<<<dim3(MCH / TNW, NPAIR / PB), 256, NSTAGEW * STAGEW>>>();
    logits_kernel<<<Bb * Hh * NSL, 256>>>(gmask, tmask);
    softmax_kernel<<<Bb * Hh, 512>>>(gmask);
    vsum_kernel<<<Bb * Hh * NSL, 256>>>();
    final_kernel<<<dim3(Bb, 4), 512>>>(Wh, bh, Wo, bo, out);
}